// round 1
// baseline (speedup 1.0000x reference)
#include <cuda_runtime.h>

#define BATCH     8192
#define IN_DIM    784
#define HID       128
#define CLASS_NUM 10
#define TREES     16
#define INTERNAL  255
#define TOTAL     511
#define DEPTH     9
#define BT        32   // batch columns per tree-kernel block

// 4 MB fp32 scratch for feats (static __device__ global: allowed, not an allocation)
__device__ float g_feats[BATCH * HID];

// ---------------------------------------------------------------------------
// GEMM1: feats = relu(X @ W1 + b1)   [8192 x 784] @ [784 x 128]
// Block: 64 rows x 128 cols, 256 threads, 4x8 register tile, k-chunk = 8
// ---------------------------------------------------------------------------
__global__ __launch_bounds__(256) void gemm1_kernel(const float* __restrict__ X,
                                                    const float* __restrict__ W1,
                                                    const float* __restrict__ b1) {
    __shared__ float sA[8 * 68];    // X chunk, transposed [k][m], padded
    __shared__ float sB[8 * 132];   // W1 chunk [k][n], padded

    const int tid = threadIdx.x;
    const int m0  = blockIdx.x * 64;
    const int tm  = tid >> 4;       // 0..15 -> 4 rows each
    const int tn  = tid & 15;       // 0..15 -> 8 cols each
    const int m0t = tm * 4;
    const int n0t = tn * 8;

    float acc[4][8];
#pragma unroll
    for (int i = 0; i < 4; i++)
#pragma unroll
        for (int j = 0; j < 8; j++) acc[i][j] = 0.f;

    for (int k0 = 0; k0 < IN_DIM; k0 += 8) {
#pragma unroll
        for (int it = 0; it < 2; it++) {           // 64x8 = 512 elems
            int e = it * 256 + tid;
            int m = e >> 3, k = e & 7;
            sA[k * 68 + m] = X[(size_t)(m0 + m) * IN_DIM + k0 + k];
        }
#pragma unroll
        for (int it = 0; it < 4; it++) {           // 8x128 = 1024 elems
            int e = it * 256 + tid;
            int k = e >> 7, n = e & 127;
            sB[k * 132 + n] = W1[(size_t)(k0 + k) * HID + n];
        }
        __syncthreads();
#pragma unroll
        for (int k = 0; k < 8; k++) {
            float4 a4  = *(const float4*)&sA[k * 68 + m0t];
            float4 b4a = *(const float4*)&sB[k * 132 + n0t];
            float4 b4b = *(const float4*)&sB[k * 132 + n0t + 4];
            float av[4] = {a4.x, a4.y, a4.z, a4.w};
            float bv[8] = {b4a.x, b4a.y, b4a.z, b4a.w, b4b.x, b4b.y, b4b.z, b4b.w};
#pragma unroll
            for (int i = 0; i < 4; i++)
#pragma unroll
                for (int j = 0; j < 8; j++) acc[i][j] += av[i] * bv[j];
        }
        __syncthreads();
    }

    float bb[8];
#pragma unroll
    for (int j = 0; j < 8; j++) bb[j] = b1[n0t + j];
#pragma unroll
    for (int i = 0; i < 4; i++) {
        float v[8];
#pragma unroll
        for (int j = 0; j < 8; j++) {
            float x = acc[i][j] + bb[j];
            v[j] = x > 0.f ? x : 0.f;
        }
        float* p = &g_feats[(size_t)(m0 + m0t + i) * HID + n0t];
        *(float4*)p       = make_float4(v[0], v[1], v[2], v[3]);
        *(float4*)(p + 4) = make_float4(v[4], v[5], v[6], v[7]);
    }
}

// ---------------------------------------------------------------------------
// Prediction: pred = feats @ W2 + b2   [8192 x 128] @ [128 x 10]
// ---------------------------------------------------------------------------
__global__ __launch_bounds__(256) void pred_kernel(const float* __restrict__ W2,
                                                   const float* __restrict__ b2,
                                                   float* __restrict__ pred) {
    __shared__ float sF[64 * 128];
    const int tid = threadIdx.x;
    const int b0  = blockIdx.x * 64;
#pragma unroll
    for (int it = 0; it < 32; it++) {
        int e = it * 256 + tid;
        sF[e] = g_feats[(size_t)b0 * HID + e];
    }
    __syncthreads();
    for (int o = tid; o < 64 * CLASS_NUM; o += 256) {
        int r = o / CLASS_NUM, c = o % CLASS_NUM;
        float s = b2[c];
#pragma unroll 8
        for (int d = 0; d < HID; d++) s += sF[r * HID + d] * W2[d * CLASS_NUM + c];
        pred[(size_t)(b0 + r) * CLASS_NUM + c] = s;
    }
}

// ---------------------------------------------------------------------------
// Tree kernel: per (tree, 32-batch tile):
//   dec[255,32] = sigmoid(nodeW[t] @ featsT + nodeb[t])   (fp32 SGEMM)
//   then unrolled DFS producing all 511 path products, coalesced stores
// ---------------------------------------------------------------------------
__device__ __forceinline__ float sigmoidf_(float x) {
    return 1.f / (1.f + __expf(-x));
}

template <int LVL>
__device__ __forceinline__ void emit(float* __restrict__ outCol,
                                     const float* __restrict__ decCol,
                                     int node, float v) {
    outCol[(size_t)node * BATCH] = v;
    if constexpr (LVL < DEPTH - 1) {   // internal node -> recurse
        float d = decCol[node * BT];
        emit<LVL + 1>(outCol, decCol, 2 * node + 1, v * d);
        emit<LVL + 1>(outCol, decCol, 2 * node + 2, v * (1.f - d));
    }
}

__global__ __launch_bounds__(256) void tree_kernel(const float* __restrict__ nodeW,
                                                   const float* __restrict__ nodeb,
                                                   float* __restrict__ outAll) {
    __shared__ float decS[256 * BT];   // 32 KB: sigmoid decisions [node][b]
    __shared__ float sA[8 * 260];      // nodeW chunk, transposed [k][node]
    __shared__ float sB[8 * 36];       // feats chunk [k][b]

    const int tid = threadIdx.x;
    const int t   = blockIdx.y;
    const int b0  = blockIdx.x * BT;

    // ---- GEMM: dec = nodeW[t] (255x128) x feats_tile^T (128x32) ----
    const int tidN = tid >> 3;          // 0..31 -> 8 nodes each
    const int tidB = tid & 7;           // 0..7  -> 4 batch each
    const int n0   = tidN * 8;
    const int bb0  = tidB * 4;

    float acc[8][4];
#pragma unroll
    for (int j = 0; j < 8; j++)
#pragma unroll
        for (int i = 0; i < 4; i++) acc[j][i] = 0.f;

    const float* Wt = nodeW + (size_t)t * INTERNAL * HID;

    for (int k0 = 0; k0 < HID; k0 += 8) {
#pragma unroll
        for (int it = 0; it < 8; it++) {           // 256x8 = 2048 elems
            int e = it * 256 + tid;
            int node = e >> 3, k = e & 7;
            sA[k * 260 + node] =
                (node < INTERNAL) ? Wt[(size_t)node * HID + k0 + k] : 0.f;
        }
        {                                          // 32x8 = 256 elems
            int b = tid >> 3, k = tid & 7;
            sB[k * 36 + b] = g_feats[(size_t)(b0 + b) * HID + k0 + k];
        }
        __syncthreads();
#pragma unroll
        for (int k = 0; k < 8; k++) {
            float4 w0 = *(const float4*)&sA[k * 260 + n0];
            float4 w1 = *(const float4*)&sA[k * 260 + n0 + 4];
            float4 f4 = *(const float4*)&sB[k * 36 + bb0];
            float wv[8] = {w0.x, w0.y, w0.z, w0.w, w1.x, w1.y, w1.z, w1.w};
            float fv[4] = {f4.x, f4.y, f4.z, f4.w};
#pragma unroll
            for (int j = 0; j < 8; j++)
#pragma unroll
                for (int i = 0; i < 4; i++) acc[j][i] += wv[j] * fv[i];
        }
        __syncthreads();
    }

    // ---- sigmoid epilogue into shared dec tile ----
#pragma unroll
    for (int j = 0; j < 8; j++) {
        int node = n0 + j;
        float nb = (node < INTERNAL) ? nodeb[t * INTERNAL + node] : 0.f;
#pragma unroll
        for (int i = 0; i < 4; i++)
            decS[node * BT + bb0 + i] = sigmoidf_(acc[j][i] + nb);
    }
    __syncthreads();

    // ---- tree path products ----
    const int b = tid & 31;            // batch column within tile
    const int s = tid >> 5;            // 0..7: level-3 subtree index
    float* outCol = outAll + (size_t)t * TOTAL * BATCH + (b0 + b);
    const float* decCol = decS + b;

    // top 7 nodes (levels 0..2): warp s (< 7) writes node s
    if (s < 7) {
        float v = 1.f;
        int n = s;
        while (n) {
            int p = (n - 1) >> 1;
            float d = decCol[p * BT];
            v *= (n == 2 * p + 1) ? d : (1.f - d);
            n = p;
        }
        outCol[(size_t)s * BATCH] = v;
    }

    // subtree rooted at level-3 node r = 7+s: 63 nodes (levels 3..8)
    const int r = 7 + s;
    float v = 1.f;
    int n = r;
    while (n) {
        int p = (n - 1) >> 1;
        float d = decCol[p * BT];
        v *= (n == 2 * p + 1) ? d : (1.f - d);
        n = p;
    }
    emit<3>(outCol, decCol, r, v);
}

// ---------------------------------------------------------------------------
extern "C" void kernel_launch(void* const* d_in, const int* in_sizes, int n_in,
                              void* d_out, int out_size) {
    const float* X     = (const float*)d_in[0];
    const float* W1    = (const float*)d_in[1];
    const float* b1    = (const float*)d_in[2];
    const float* W2    = (const float*)d_in[3];
    const float* b2    = (const float*)d_in[4];
    const float* nodeW = (const float*)d_in[5];
    const float* nodeb = (const float*)d_in[6];

    float* pred   = (float*)d_out;                                 // [8192, 10]
    float* outAll = (float*)d_out + (size_t)BATCH * CLASS_NUM;     // [16, 511, 8192]

    gemm1_kernel<<<BATCH / 64, 256>>>(X, W1, b1);
    pred_kernel<<<BATCH / 64, 256>>>(W2, b2, pred);
    tree_kernel<<<dim3(BATCH / BT, TREES), 256>>>(nodeW, nodeb, outAll);
}

// round 2
// speedup vs baseline: 1.1599x; 1.1599x over previous
#include <cuda_runtime.h>

typedef unsigned long long u64;

#define BATCH     8192
#define IN_DIM    784
#define HID       128
#define CLASS_NUM 10
#define TREES     16
#define INTERNAL  255
#define TOTAL     511
#define DEPTH     9
#define BT        64    // batch columns per tree-kernel block

__device__ float g_feats[BATCH * HID];   // 4 MB static scratch

// ---------------- f32x2 packed helpers (sm_103a dual-issue FMA pipe) --------
__device__ __forceinline__ u64 splat2(float x) {
    u64 r; asm("mov.b64 %0, {%1, %1};" : "=l"(r) : "f"(x)); return r;
}
__device__ __forceinline__ void fma2(u64& d, u64 a, u64 b) {
    asm("fma.rn.f32x2 %0, %1, %2, %0;" : "+l"(d) : "l"(a), "l"(b));
}
__device__ __forceinline__ float lo32(u64 v) { return __uint_as_float((unsigned)v); }
__device__ __forceinline__ float hi32(u64 v) { return __uint_as_float((unsigned)(v >> 32)); }

__device__ __forceinline__ float sigmoidf_(float x) {
    return 1.f / (1.f + __expf(-x));
}

// ---------------------------------------------------------------------------
// GEMM1: feats = relu(X @ W1 + b1)   [8192 x 784] @ [784 x 128]
// Block: 32 rows x 128 cols, 128 threads, 4m x 8n tile (n packed as f32x2),
// k-chunk 16 with register-staged prefetch.
// ---------------------------------------------------------------------------
#define G1_AP 36
#define G1_BP 132
__global__ __launch_bounds__(128) void gemm1_kernel(const float* __restrict__ X,
                                                    const float* __restrict__ W1,
                                                    const float* __restrict__ b1) {
    __shared__ float sA[16 * G1_AP];   // X chunk transposed [k][m]
    __shared__ float sB[16 * G1_BP];   // W1 chunk [k][n]

    const int tid = threadIdx.x;
    const int m0  = blockIdx.x * 32;

    // load indices
    const int lm = tid >> 2;           // 0..31
    const int lq = tid & 3;            // 0..3 -> k-offset lq*4
    const int bk = tid >> 5;           // 0..3 (base k within group of 4)
    const int bc = (tid & 31) * 4;     // col

    // compute indices
    const int tm  = tid >> 4;          // 0..7
    const int tn  = tid & 15;          // 0..15
    const int m0t = tm * 4;
    const int n0t = tn * 8;

    u64 acc[4][4];
#pragma unroll
    for (int i = 0; i < 4; i++)
#pragma unroll
        for (int j = 0; j < 4; j++) acc[i][j] = 0ull;

    float4 aReg;
    float4 bReg[4];

    // prefetch chunk 0
    aReg = *(const float4*)&X[(size_t)(m0 + lm) * IN_DIM + lq * 4];
#pragma unroll
    for (int it = 0; it < 4; it++)
        bReg[it] = *(const float4*)&W1[(size_t)(it * 4 + bk) * HID + bc];

    for (int c = 0; c < IN_DIM / 16; c++) {
        // store staged regs to smem
        sA[(lq * 4 + 0) * G1_AP + lm] = aReg.x;
        sA[(lq * 4 + 1) * G1_AP + lm] = aReg.y;
        sA[(lq * 4 + 2) * G1_AP + lm] = aReg.z;
        sA[(lq * 4 + 3) * G1_AP + lm] = aReg.w;
#pragma unroll
        for (int it = 0; it < 4; it++)
            *(float4*)&sB[(it * 4 + bk) * G1_BP + bc] = bReg[it];
        __syncthreads();

        // prefetch next chunk (overlaps compute)
        if (c + 1 < IN_DIM / 16) {
            int k0 = (c + 1) * 16;
            aReg = *(const float4*)&X[(size_t)(m0 + lm) * IN_DIM + k0 + lq * 4];
#pragma unroll
            for (int it = 0; it < 4; it++)
                bReg[it] = *(const float4*)&W1[(size_t)(k0 + it * 4 + bk) * HID + bc];
        }

#pragma unroll
        for (int k = 0; k < 16; k++) {
            float4 av = *(const float4*)&sA[k * G1_AP + m0t];
            ulonglong2 b01 = *(const ulonglong2*)&sB[k * G1_BP + n0t];
            ulonglong2 b23 = *(const ulonglong2*)&sB[k * G1_BP + n0t + 4];
            u64 bp[4] = {b01.x, b01.y, b23.x, b23.y};
            u64 as[4] = {splat2(av.x), splat2(av.y), splat2(av.z), splat2(av.w)};
#pragma unroll
            for (int i = 0; i < 4; i++)
#pragma unroll
                for (int j = 0; j < 4; j++) fma2(acc[i][j], as[i], bp[j]);
        }
        __syncthreads();
    }

    // epilogue: + b1, relu, store
    float bb[8];
#pragma unroll
    for (int j = 0; j < 8; j++) bb[j] = b1[n0t + j];
#pragma unroll
    for (int i = 0; i < 4; i++) {
        float v[8];
#pragma unroll
        for (int j = 0; j < 4; j++) {
            v[2 * j]     = lo32(acc[i][j]) + bb[2 * j];
            v[2 * j + 1] = hi32(acc[i][j]) + bb[2 * j + 1];
        }
#pragma unroll
        for (int j = 0; j < 8; j++) v[j] = v[j] > 0.f ? v[j] : 0.f;
        float* p = &g_feats[(size_t)(m0 + m0t + i) * HID + n0t];
        *(float4*)p       = make_float4(v[0], v[1], v[2], v[3]);
        *(float4*)(p + 4) = make_float4(v[4], v[5], v[6], v[7]);
    }
}

// ---------------------------------------------------------------------------
// Prediction: pred = feats @ W2 + b2   [8192 x 128] @ [128 x 10]
// ---------------------------------------------------------------------------
__global__ __launch_bounds__(256) void pred_kernel(const float* __restrict__ W2,
                                                   const float* __restrict__ b2,
                                                   float* __restrict__ pred) {
    __shared__ float sF[64 * 132];           // padded feats tile
    __shared__ float sW2[HID * CLASS_NUM];   // 5 KB
    const int tid = threadIdx.x;
    const int b0  = blockIdx.x * 64;
#pragma unroll
    for (int it = 0; it < 32; it++) {
        int e = it * 256 + tid;
        int r = e >> 7, d = e & 127;
        sF[r * 132 + d] = g_feats[(size_t)(b0 + r) * HID + d];
    }
    for (int e = tid; e < HID * CLASS_NUM; e += 256) sW2[e] = W2[e];
    __syncthreads();
    for (int o = tid; o < 64 * CLASS_NUM; o += 256) {
        int r = o / CLASS_NUM, c = o % CLASS_NUM;
        float s = b2[c];
#pragma unroll 8
        for (int d = 0; d < HID; d++) s += sF[r * 132 + d] * sW2[d * CLASS_NUM + c];
        pred[(size_t)(b0 + r) * CLASS_NUM + c] = s;
    }
}

// ---------------------------------------------------------------------------
// Tree kernel: per (tree, 64-batch tile):
//   dec[255,64] = sigmoid(nodeW[t] @ featsT + nodeb[t])  (f32x2 SGEMM)
//   then unrolled DFS producing all 511 path products
// Block: 512 threads; dynamic smem: decS 64KB + sA 16.5KB + sB 4.25KB
// ---------------------------------------------------------------------------
#define T_NPAD 264
#define T_BPAD 68
#define T_SMEM_FLOATS (256 * BT + 16 * T_NPAD + 16 * T_BPAD)

template <int LVL>
__device__ __forceinline__ void emit(float* __restrict__ outCol,
                                     const float* __restrict__ decCol,
                                     int node, float v) {
    outCol[(size_t)node * BATCH] = v;
    if constexpr (LVL < DEPTH - 1) {
        float d = decCol[node * BT];
        emit<LVL + 1>(outCol, decCol, 2 * node + 1, v * d);
        emit<LVL + 1>(outCol, decCol, 2 * node + 2, v * (1.f - d));
    }
}

__global__ __launch_bounds__(512) void tree_kernel(const float* __restrict__ nodeW,
                                                   const float* __restrict__ nodeb,
                                                   float* __restrict__ outAll) {
    extern __shared__ float sm[];
    float* decS = sm;                       // [256][BT]
    float* sA   = sm + 256 * BT;            // [16][T_NPAD] transposed nodeW chunk
    float* sB   = sA + 16 * T_NPAD;         // [16][T_BPAD] feats chunk

    const int tid = threadIdx.x;
    const int t   = blockIdx.y;
    const int b0  = blockIdx.x * BT;
    const float* Wt = nodeW + (size_t)t * INTERNAL * HID;

    // load indices
    const int lnode = tid >> 1;             // 0..255
    const int lhalf = tid & 1;              // k-offset lhalf*8
    const int lb    = tid >> 3;             // 0..63
    const int lp    = tid & 7;              // k-offset lp*2

    // compute indices: 8 nodes (4 pairs) x 4 batch per thread
    const int tidN = tid >> 4;              // 0..31
    const int tidB = tid & 15;              // 0..15
    const int n0   = tidN * 8;
    const int bb0  = tidB * 4;

    u64 acc[4][4];
#pragma unroll
    for (int p = 0; p < 4; p++)
#pragma unroll
        for (int i = 0; i < 4; i++) acc[p][i] = 0ull;

    float aReg[8];
    float bReg[2];

    // prefetch chunk 0
    if (lnode < INTERNAL) {
        float4 x0 = *(const float4*)&Wt[(size_t)lnode * HID + lhalf * 8];
        float4 x1 = *(const float4*)&Wt[(size_t)lnode * HID + lhalf * 8 + 4];
        aReg[0]=x0.x; aReg[1]=x0.y; aReg[2]=x0.z; aReg[3]=x0.w;
        aReg[4]=x1.x; aReg[5]=x1.y; aReg[6]=x1.z; aReg[7]=x1.w;
    } else {
#pragma unroll
        for (int j = 0; j < 8; j++) aReg[j] = 0.f;
    }
    {
        float2 f2 = *(const float2*)&g_feats[(size_t)(b0 + lb) * HID + lp * 2];
        bReg[0] = f2.x; bReg[1] = f2.y;
    }

    for (int c = 0; c < HID / 16; c++) {
#pragma unroll
        for (int j = 0; j < 8; j++) sA[(lhalf * 8 + j) * T_NPAD + lnode] = aReg[j];
        sB[(lp * 2 + 0) * T_BPAD + lb] = bReg[0];
        sB[(lp * 2 + 1) * T_BPAD + lb] = bReg[1];
        __syncthreads();

        if (c + 1 < HID / 16) {
            int k0 = (c + 1) * 16;
            if (lnode < INTERNAL) {
                float4 x0 = *(const float4*)&Wt[(size_t)lnode * HID + k0 + lhalf * 8];
                float4 x1 = *(const float4*)&Wt[(size_t)lnode * HID + k0 + lhalf * 8 + 4];
                aReg[0]=x0.x; aReg[1]=x0.y; aReg[2]=x0.z; aReg[3]=x0.w;
                aReg[4]=x1.x; aReg[5]=x1.y; aReg[6]=x1.z; aReg[7]=x1.w;
            }
            float2 f2 = *(const float2*)&g_feats[(size_t)(b0 + lb) * HID + k0 + lp * 2];
            bReg[0] = f2.x; bReg[1] = f2.y;
        }

#pragma unroll
        for (int k = 0; k < 16; k++) {
            ulonglong2 w01 = *(const ulonglong2*)&sA[k * T_NPAD + n0];
            ulonglong2 w23 = *(const ulonglong2*)&sA[k * T_NPAD + n0 + 4];
            float4 f = *(const float4*)&sB[k * T_BPAD + bb0];
            u64 wp[4] = {w01.x, w01.y, w23.x, w23.y};
            u64 fs[4] = {splat2(f.x), splat2(f.y), splat2(f.z), splat2(f.w)};
#pragma unroll
            for (int p = 0; p < 4; p++)
#pragma unroll
                for (int i = 0; i < 4; i++) fma2(acc[p][i], wp[p], fs[i]);
        }
        __syncthreads();
    }

    // ---- sigmoid epilogue into shared dec tile (node pairs in lo/hi) ----
#pragma unroll
    for (int p = 0; p < 4; p++) {
        int nA = n0 + 2 * p, nB = nA + 1;
        float biasA = (nA < INTERNAL) ? nodeb[t * INTERNAL + nA] : 0.f;
        float biasB = (nB < INTERNAL) ? nodeb[t * INTERNAL + nB] : 0.f;
#pragma unroll
        for (int i = 0; i < 4; i++) {
            decS[nA * BT + bb0 + i] = sigmoidf_(lo32(acc[p][i]) + biasA);
            decS[nB * BT + bb0 + i] = sigmoidf_(hi32(acc[p][i]) + biasB);
        }
    }
    __syncthreads();

    // ---- tree path products: 64 columns x 8 subtree threads ----
    const int b = tid & 63;
    const int s = tid >> 6;                 // 0..7: level-3 subtree
    float* outCol = outAll + (size_t)t * TOTAL * BATCH + (b0 + b);
    const float* decCol = decS + b;

    if (s < 7) {                            // top 7 nodes (levels 0..2)
        float v = 1.f;
        int n = s;
        while (n) {
            int p = (n - 1) >> 1;
            float d = decCol[p * BT];
            v *= (n == 2 * p + 1) ? d : (1.f - d);
            n = p;
        }
        outCol[(size_t)s * BATCH] = v;
    }

    const int r = 7 + s;                    // level-3 root
    float v = 1.f;
    int n = r;
    while (n) {
        int p = (n - 1) >> 1;
        float d = decCol[p * BT];
        v *= (n == 2 * p + 1) ? d : (1.f - d);
        n = p;
    }
    emit<3>(outCol, decCol, r, v);
}

// ---------------------------------------------------------------------------
extern "C" void kernel_launch(void* const* d_in, const int* in_sizes, int n_in,
                              void* d_out, int out_size) {
    const float* X     = (const float*)d_in[0];
    const float* W1    = (const float*)d_in[1];
    const float* b1    = (const float*)d_in[2];
    const float* W2    = (const float*)d_in[3];
    const float* b2    = (const float*)d_in[4];
    const float* nodeW = (const float*)d_in[5];
    const float* nodeb = (const float*)d_in[6];

    float* pred   = (float*)d_out;                               // [8192, 10]
    float* outAll = (float*)d_out + (size_t)BATCH * CLASS_NUM;   // [16, 511, 8192]

    static int smem_set = 0;
    (void)smem_set;
    cudaFuncSetAttribute(tree_kernel, cudaFuncAttributeMaxDynamicSharedMemorySize,
                         T_SMEM_FLOATS * (int)sizeof(float));

    gemm1_kernel<<<BATCH / 32, 128>>>(X, W1, b1);
    pred_kernel<<<BATCH / 64, 256>>>(W2, b2, pred);
    tree_kernel<<<dim3(BATCH / BT, TREES), 512,
                  T_SMEM_FLOATS * (int)sizeof(float)>>>(nodeW, nodeb, outAll);
}

// round 4
// speedup vs baseline: 1.3568x; 1.1698x over previous
#include <cuda_runtime.h>
#include <cuda_bf16.h>
#include <cstdint>

typedef unsigned long long u64;

#define BATCH     8192
#define IN_DIM    784
#define HID       128
#define CLASS_NUM 10
#define TREES     16
#define INTERNAL  255
#define TOTAL     511
#define DEPTH     9

// ---------------- static scratch (no allocations) ---------------------------
__device__ float          g_feats[BATCH * HID];          // fp32 feats (pred path)
__device__ unsigned short g_fH[BATCH * HID];             // feats hi bf16 bits
__device__ unsigned short g_fL[BATCH * HID];             // feats lo bf16 bits
__device__ unsigned short g_nwH[TREES * 256 * HID];      // nodeW hi (node 255 = 0 pad)
__device__ unsigned short g_nwL[TREES * 256 * HID];      // nodeW lo

// ---------------- helpers ----------------------------------------------------
__device__ __forceinline__ u64 splat2(float x) {
    u64 r; asm("mov.b64 %0, {%1, %1};" : "=l"(r) : "f"(x)); return r;
}
__device__ __forceinline__ void fma2(u64& d, u64 a, u64 b) {
    asm("fma.rn.f32x2 %0, %1, %2, %0;" : "+l"(d) : "l"(a), "l"(b));
}
__device__ __forceinline__ float lo32(u64 v) { return __uint_as_float((unsigned)v); }
__device__ __forceinline__ float hi32(u64 v) { return __uint_as_float((unsigned)(v >> 32)); }
__device__ __forceinline__ float sigmoidf_(float x) { return 1.f / (1.f + __expf(-x)); }

__device__ __forceinline__ unsigned bf16_bits(float x) {   // RNE
    uint32_t u = __float_as_uint(x);
    return (u + 0x7FFFu + ((u >> 16) & 1u)) >> 16;
}
__device__ __forceinline__ float bf16_val(unsigned bits) {
    return __uint_as_float(bits << 16);
}

// warp-level bf16 MMA: D[16x8] += A[16x16] * B[16x8]  (fp32 accum)
__device__ __forceinline__ void mma16816(float* c, uint32_t a0, uint32_t a1,
                                         uint32_t a2, uint32_t a3,
                                         uint32_t b0, uint32_t b1) {
    asm volatile(
        "mma.sync.aligned.m16n8k16.row.col.f32.bf16.bf16.f32 "
        "{%0,%1,%2,%3}, {%4,%5,%6,%7}, {%8,%9}, {%0,%1,%2,%3};"
        : "+f"(c[0]), "+f"(c[1]), "+f"(c[2]), "+f"(c[3])
        : "r"(a0), "r"(a1), "r"(a2), "r"(a3), "r"(b0), "r"(b1));
}

// ---------------------------------------------------------------------------
// nodeW -> bf16 hi/lo split, padded to 256 nodes
// ---------------------------------------------------------------------------
__global__ __launch_bounds__(256) void conv_nodeW_kernel(const float* __restrict__ nodeW) {
    int idx  = blockIdx.x * 256 + threadIdx.x;      // 0 .. 16*256*128-1
    int k    = idx & 127;
    int node = (idx >> 7) & 255;
    int t    = idx >> 15;
    float w  = (node < INTERNAL) ? nodeW[((size_t)t * INTERNAL + node) * HID + k] : 0.f;
    unsigned hb = bf16_bits(w);
    float lf = w - bf16_val(hb);
    g_nwH[idx] = (unsigned short)hb;
    g_nwL[idx] = (unsigned short)bf16_bits(lf);
}

// ---------------------------------------------------------------------------
// GEMM1: feats = relu(X @ W1 + b1); also emits bf16 hi/lo feats
// ---------------------------------------------------------------------------
#define G1_AP 36
#define G1_BP 132
__global__ __launch_bounds__(128) void gemm1_kernel(const float* __restrict__ X,
                                                    const float* __restrict__ W1,
                                                    const float* __restrict__ b1) {
    __shared__ float sA[16 * G1_AP];
    __shared__ float sB[16 * G1_BP];

    const int tid = threadIdx.x;
    const int m0  = blockIdx.x * 32;

    const int lm = tid >> 2;
    const int lq = tid & 3;
    const int bk = tid >> 5;
    const int bc = (tid & 31) * 4;

    const int tm  = tid >> 4;
    const int tn  = tid & 15;
    const int m0t = tm * 4;
    const int n0t = tn * 8;

    u64 acc[4][4];
#pragma unroll
    for (int i = 0; i < 4; i++)
#pragma unroll
        for (int j = 0; j < 4; j++) acc[i][j] = 0ull;

    float4 aReg;
    float4 bReg[4];

    aReg = *(const float4*)&X[(size_t)(m0 + lm) * IN_DIM + lq * 4];
#pragma unroll
    for (int it = 0; it < 4; it++)
        bReg[it] = *(const float4*)&W1[(size_t)(it * 4 + bk) * HID + bc];

    for (int c = 0; c < IN_DIM / 16; c++) {
        sA[(lq * 4 + 0) * G1_AP + lm] = aReg.x;
        sA[(lq * 4 + 1) * G1_AP + lm] = aReg.y;
        sA[(lq * 4 + 2) * G1_AP + lm] = aReg.z;
        sA[(lq * 4 + 3) * G1_AP + lm] = aReg.w;
#pragma unroll
        for (int it = 0; it < 4; it++)
            *(float4*)&sB[(it * 4 + bk) * G1_BP + bc] = bReg[it];
        __syncthreads();

        if (c + 1 < IN_DIM / 16) {
            int k0 = (c + 1) * 16;
            aReg = *(const float4*)&X[(size_t)(m0 + lm) * IN_DIM + k0 + lq * 4];
#pragma unroll
            for (int it = 0; it < 4; it++)
                bReg[it] = *(const float4*)&W1[(size_t)(k0 + it * 4 + bk) * HID + bc];
        }

#pragma unroll
        for (int k = 0; k < 16; k++) {
            float4 av = *(const float4*)&sA[k * G1_AP + m0t];
            ulonglong2 b01 = *(const ulonglong2*)&sB[k * G1_BP + n0t];
            ulonglong2 b23 = *(const ulonglong2*)&sB[k * G1_BP + n0t + 4];
            u64 bp[4] = {b01.x, b01.y, b23.x, b23.y};
            u64 as[4] = {splat2(av.x), splat2(av.y), splat2(av.z), splat2(av.w)};
#pragma unroll
            for (int i = 0; i < 4; i++)
#pragma unroll
                for (int j = 0; j < 4; j++) fma2(acc[i][j], as[i], bp[j]);
        }
        __syncthreads();
    }

    float bb[8];
#pragma unroll
    for (int j = 0; j < 8; j++) bb[j] = b1[n0t + j];
#pragma unroll
    for (int i = 0; i < 4; i++) {
        float v[8];
#pragma unroll
        for (int j = 0; j < 4; j++) {
            v[2 * j]     = lo32(acc[i][j]) + bb[2 * j];
            v[2 * j + 1] = hi32(acc[i][j]) + bb[2 * j + 1];
        }
        unsigned hb[8], lb[8];
#pragma unroll
        for (int j = 0; j < 8; j++) {
            v[j] = v[j] > 0.f ? v[j] : 0.f;
            hb[j] = bf16_bits(v[j]);
            lb[j] = bf16_bits(v[j] - bf16_val(hb[j]));
        }
        size_t row = (size_t)(m0 + m0t + i);
        float* p = &g_feats[row * HID + n0t];
        *(float4*)p       = make_float4(v[0], v[1], v[2], v[3]);
        *(float4*)(p + 4) = make_float4(v[4], v[5], v[6], v[7]);
        uint4 uh, ul;
        uh.x = hb[0] | (hb[1] << 16); uh.y = hb[2] | (hb[3] << 16);
        uh.z = hb[4] | (hb[5] << 16); uh.w = hb[6] | (hb[7] << 16);
        ul.x = lb[0] | (lb[1] << 16); ul.y = lb[2] | (lb[3] << 16);
        ul.z = lb[4] | (lb[5] << 16); ul.w = lb[6] | (lb[7] << 16);
        *(uint4*)&g_fH[row * HID + n0t] = uh;
        *(uint4*)&g_fL[row * HID + n0t] = ul;
    }
}

// ---------------------------------------------------------------------------
// Prediction: pred = feats @ W2 + b2
// ---------------------------------------------------------------------------
__global__ __launch_bounds__(256) void pred_kernel(const float* __restrict__ W2,
                                                   const float* __restrict__ b2,
                                                   float* __restrict__ pred) {
    __shared__ float sF[64 * 132];
    __shared__ float sW2[HID * CLASS_NUM];
    const int tid = threadIdx.x;
    const int b0  = blockIdx.x * 64;
#pragma unroll
    for (int it = 0; it < 32; it++) {
        int e = it * 256 + tid;
        int r = e >> 7, d = e & 127;
        sF[r * 132 + d] = g_feats[(size_t)(b0 + r) * HID + d];
    }
    for (int e = tid; e < HID * CLASS_NUM; e += 256) sW2[e] = W2[e];
    __syncthreads();
    for (int o = tid; o < 64 * CLASS_NUM; o += 256) {
        int r = o / CLASS_NUM, c = o % CLASS_NUM;
        float s = b2[c];
#pragma unroll 8
        for (int d = 0; d < HID; d++) s += sF[r * 132 + d] * sW2[d * CLASS_NUM + c];
        pred[(size_t)(b0 + r) * CLASS_NUM + c] = s;
    }
}

// ---------------------------------------------------------------------------
// Tree kernel (mma.sync bf16, 3-term hi/lo split):
//   per (tree, 64-batch tile): D[64b x 256n] = Ah·Bh + Al·Bh + Ah·Bl
//   -> sigmoid -> smem dec tile -> tree path products
// ---------------------------------------------------------------------------
#define MB    64
#define DSTR  68                       // dec tile stride (pad 4 -> conflict-free)
#define KSTR  17                       // k-pair stride in u32
#define KC    32                       // k per chunk

#define OFF_DEC 0
#define OFF_FH  (256 * DSTR * 4)                   // 69632
#define OFF_FL  (OFF_FH + MB * KSTR * 4)           // +4352
#define OFF_WH  (OFF_FL + MB * KSTR * 4)           // +4352
#define OFF_WL  (OFF_WH + 256 * KSTR * 4)          // +17408
#define OFF_NB  (OFF_WL + 256 * KSTR * 4)          // +17408
#define TREE_SMEM (OFF_NB + 256 * 4)               // 114176 bytes

template <int LVL>
__device__ __forceinline__ void emit(float* __restrict__ outCol,
                                     const float* __restrict__ decCol,
                                     int node, float v) {
    outCol[(size_t)node * BATCH] = v;
    if constexpr (LVL < DEPTH - 1) {
        float d = decCol[node * DSTR];
        emit<LVL + 1>(outCol, decCol, 2 * node + 1, v * d);
        emit<LVL + 1>(outCol, decCol, 2 * node + 2, v * (1.f - d));
    }
}

__global__ __launch_bounds__(512) void tree_mma_kernel(const float* __restrict__ nodeb,
                                                       float* __restrict__ outAll) {
    extern __shared__ char smem[];
    float*    decS = (float*)(smem + OFF_DEC);
    uint32_t* sFh  = (uint32_t*)(smem + OFF_FH);
    uint32_t* sFl  = (uint32_t*)(smem + OFF_FL);
    uint32_t* sWh  = (uint32_t*)(smem + OFF_WH);
    uint32_t* sWl  = (uint32_t*)(smem + OFF_WL);
    float*    sNB  = (float*)(smem + OFF_NB);

    const int tid  = threadIdx.x;
    const int wid  = tid >> 5;
    const int lane = tid & 31;
    const int t    = blockIdx.y;
    const int b0   = blockIdx.x * MB;

    if (tid < 256)
        sNB[tid] = (tid < INTERNAL) ? nodeb[t * INTERNAL + tid] : 0.f;

    const int wb  = wid >> 2;     // 0..3: 16-batch tile
    const int wn  = wid & 3;      // 0..3: 64-node tile
    const int grp = lane >> 2;    // 0..7
    const int kp  = lane & 3;     // 0..3

    float acc[8][4];
#pragma unroll
    for (int ni = 0; ni < 8; ni++)
#pragma unroll
        for (int r = 0; r < 4; r++) acc[ni][r] = 0.f;

    const size_t wbase = (size_t)t * 256 * HID;

    for (int c = 0; c < HID / KC; c++) {
        // ---- stage chunk c into smem ----
        {
            int i = tid & 255, b = i >> 2, q = i & 3;
            const unsigned short* srcF = (tid < 256) ? g_fH : g_fL;
            uint4 v = *(const uint4*)(srcF + (size_t)(b0 + b) * HID + c * KC + q * 8);
            uint32_t* dst = ((tid < 256) ? sFh : sFl) + b * KSTR + q * 4;
            dst[0] = v.x; dst[1] = v.y; dst[2] = v.z; dst[3] = v.w;
        }
#pragma unroll
        for (int rep = 0; rep < 2; rep++) {
            int i = tid + rep * 512, n = i >> 2, q = i & 3;
            uint4 vh = *(const uint4*)(g_nwH + wbase + (size_t)n * HID + c * KC + q * 8);
            uint4 vl = *(const uint4*)(g_nwL + wbase + (size_t)n * HID + c * KC + q * 8);
            uint32_t* dh = sWh + n * KSTR + q * 4;
            uint32_t* dl = sWl + n * KSTR + q * 4;
            dh[0] = vh.x; dh[1] = vh.y; dh[2] = vh.z; dh[3] = vh.w;
            dl[0] = vl.x; dl[1] = vl.y; dl[2] = vl.z; dl[3] = vl.w;
        }
        __syncthreads();

        // ---- MMAs: 2 k-steps x 8 n-tiles x 3 terms ----
#pragma unroll
        for (int s = 0; s < 2; s++) {
            const int rb = wb * 16;
            const int ko = s * 8 + kp;
            uint32_t ah0 = sFh[(rb + grp)     * KSTR + ko];
            uint32_t ah1 = sFh[(rb + grp + 8) * KSTR + ko];
            uint32_t ah2 = sFh[(rb + grp)     * KSTR + ko + 4];
            uint32_t ah3 = sFh[(rb + grp + 8) * KSTR + ko + 4];
            uint32_t al0 = sFl[(rb + grp)     * KSTR + ko];
            uint32_t al1 = sFl[(rb + grp + 8) * KSTR + ko];
            uint32_t al2 = sFl[(rb + grp)     * KSTR + ko + 4];
            uint32_t al3 = sFl[(rb + grp + 8) * KSTR + ko + 4];
#pragma unroll
            for (int ni = 0; ni < 8; ni++) {
                int nrow = wn * 64 + ni * 8 + grp;
                uint32_t bh0 = sWh[nrow * KSTR + ko];
                uint32_t bh1 = sWh[nrow * KSTR + ko + 4];
                mma16816(acc[ni], ah0, ah1, ah2, ah3, bh0, bh1);   // Ah*Bh
                mma16816(acc[ni], al0, al1, al2, al3, bh0, bh1);   // Al*Bh
                uint32_t bl0 = sWl[nrow * KSTR + ko];
                uint32_t bl1 = sWl[nrow * KSTR + ko + 4];
                mma16816(acc[ni], ah0, ah1, ah2, ah3, bl0, bl1);   // Ah*Bl
            }
        }
        __syncthreads();
    }

    // ---- epilogue: + bias, sigmoid -> dec tile ----
#pragma unroll
    for (int ni = 0; ni < 8; ni++) {
        int nbase = wn * 64 + ni * 8 + kp * 2;
        int bb    = wb * 16 + grp;
#pragma unroll
        for (int r = 0; r < 4; r++) {
            int node = nbase + (r & 1);
            int b    = bb + (r >> 1) * 8;
            if (node < INTERNAL)
                decS[node * DSTR + b] = sigmoidf_(acc[ni][r] + sNB[node]);
        }
    }
    __syncthreads();

    // ---- tree path products: 64 cols x 8 subtree threads ----
    {
        const int colb = tid & 63;
        const int q    = tid >> 6;          // 0..7
        float* outCol = outAll + (size_t)t * TOTAL * BATCH + (b0 + colb);
        const float* decCol = decS + colb;

        if (q < 7) {                        // top 7 nodes (levels 0..2)
            float v = 1.f; int x = q;
            while (x) {
                int p = (x - 1) >> 1;
                float d = decCol[p * DSTR];
                v *= (x == 2 * p + 1) ? d : (1.f - d);
                x = p;
            }
            outCol[(size_t)q * BATCH] = v;
        }

        const int rN = 7 + q;               // level-3 subtree root
        float v = 1.f; int x = rN;
        while (x) {
            int p = (x - 1) >> 1;
            float d = decCol[p * DSTR];
            v *= (x == 2 * p + 1) ? d : (1.f - d);
            x = p;
        }
        emit<3>(outCol, decCol, rN, v);
    }
}

// ---------------------------------------------------------------------------
extern "C" void kernel_launch(void* const* d_in, const int* in_sizes, int n_in,
                              void* d_out, int out_size) {
    const float* X     = (const float*)d_in[0];
    const float* W1    = (const float*)d_in[1];
    const float* b1    = (const float*)d_in[2];
    const float* W2    = (const float*)d_in[3];
    const float* b2    = (const float*)d_in[4];
    const float* nodeW = (const float*)d_in[5];
    const float* nodeb = (const float*)d_in[6];

    float* pred   = (float*)d_out;                               // [8192, 10]
    float* outAll = (float*)d_out + (size_t)BATCH * CLASS_NUM;   // [16, 511, 8192]

    cudaFuncSetAttribute(tree_mma_kernel, cudaFuncAttributeMaxDynamicSharedMemorySize,
                         TREE_SMEM);

    conv_nodeW_kernel<<<TREES * 256 * HID / 256, 256>>>(nodeW);
    gemm1_kernel<<<BATCH / 32, 128>>>(X, W1, b1);
    tree_mma_kernel<<<dim3(BATCH / MB, TREES), 512, TREE_SMEM>>>(nodeb, outAll);
    pred_kernel<<<BATCH / 64, 256>>>(W2, b2, pred);
}

// round 5
// speedup vs baseline: 1.6678x; 1.2292x over previous
#include <cuda_runtime.h>
#include <cuda_bf16.h>
#include <cstdint>

typedef unsigned long long u64;

#define BATCH     8192
#define IN_DIM    784
#define INP       800            // padded IN_DIM (multiple of 32)
#define HID       128
#define CLASS_NUM 10
#define TREES     16
#define INTERNAL  255
#define TOTAL     511
#define DEPTH     9

// ---------------- static scratch (no allocations) ---------------------------
__device__ float          g_feats[BATCH * HID];
__device__ unsigned short g_fH[BATCH * HID];
__device__ unsigned short g_fL[BATCH * HID];
__device__ unsigned short g_nwH[TREES * 256 * HID];
__device__ unsigned short g_nwL[TREES * 256 * HID];
__device__ unsigned short g_xH[BATCH * INP];
__device__ unsigned short g_xL[BATCH * INP];
__device__ unsigned short g_w1H[HID * INP];     // W1 transposed [hid][k]
__device__ unsigned short g_w1L[HID * INP];

// ---------------- helpers ----------------------------------------------------
__device__ __forceinline__ float sigmoidf_(float x) { return 1.f / (1.f + __expf(-x)); }

__device__ __forceinline__ unsigned bf16_bits(float x) {   // RNE
    uint32_t u = __float_as_uint(x);
    return (u + 0x7FFFu + ((u >> 16) & 1u)) >> 16;
}
__device__ __forceinline__ float bf16_val(unsigned bits) {
    return __uint_as_float(bits << 16);
}

__device__ __forceinline__ uint32_t smem_u32(const void* p) {
    uint32_t a;
    asm("{ .reg .u64 t; cvta.to.shared.u64 t, %1; cvt.u32.u64 %0, t; }" : "=r"(a) : "l"(p));
    return a;
}
__device__ __forceinline__ void cp16(uint32_t dst, const void* src) {
    asm volatile("cp.async.ca.shared.global [%0], [%1], 16;" :: "r"(dst), "l"(src));
}
__device__ __forceinline__ void cp_commit() {
    asm volatile("cp.async.commit_group;" ::: "memory");
}
__device__ __forceinline__ void cp_wait0() {
    asm volatile("cp.async.wait_group 0;" ::: "memory");
}

// warp-level bf16 MMA: D[16x8] += A[16x16] * B[16x8]  (fp32 accum)
__device__ __forceinline__ void mma16816(float* c, uint32_t a0, uint32_t a1,
                                         uint32_t a2, uint32_t a3,
                                         uint32_t b0, uint32_t b1) {
    asm volatile(
        "mma.sync.aligned.m16n8k16.row.col.f32.bf16.bf16.f32 "
        "{%0,%1,%2,%3}, {%4,%5,%6,%7}, {%8,%9}, {%0,%1,%2,%3};"
        : "+f"(c[0]), "+f"(c[1]), "+f"(c[2]), "+f"(c[3])
        : "r"(a0), "r"(a1), "r"(a2), "r"(a3), "r"(b0), "r"(b1));
}

// ---------------------------------------------------------------------------
// conversion kernels
// ---------------------------------------------------------------------------
__global__ __launch_bounds__(256) void conv_nodeW_kernel(const float* __restrict__ nodeW) {
    int idx  = blockIdx.x * 256 + threadIdx.x;
    int k    = idx & 127;
    int node = (idx >> 7) & 255;
    int t    = idx >> 15;
    float w  = (node < INTERNAL) ? nodeW[((size_t)t * INTERNAL + node) * HID + k] : 0.f;
    unsigned hb = bf16_bits(w);
    g_nwH[idx] = (unsigned short)hb;
    g_nwL[idx] = (unsigned short)bf16_bits(w - bf16_val(hb));
}

__global__ __launch_bounds__(256) void conv_X_kernel(const float* __restrict__ X) {
    int row = blockIdx.x;
    for (int k = threadIdx.x; k < INP; k += 256) {
        float x = (k < IN_DIM) ? X[(size_t)row * IN_DIM + k] : 0.f;
        unsigned hb = bf16_bits(x);
        g_xH[(size_t)row * INP + k] = (unsigned short)hb;
        g_xL[(size_t)row * INP + k] = (unsigned short)bf16_bits(x - bf16_val(hb));
    }
}

__global__ __launch_bounds__(256) void conv_W1_kernel(const float* __restrict__ W1) {
    int n = blockIdx.x;
    for (int k = threadIdx.x; k < INP; k += 256) {
        float w = (k < IN_DIM) ? W1[(size_t)k * HID + n] : 0.f;
        unsigned hb = bf16_bits(w);
        g_w1H[(size_t)n * INP + k] = (unsigned short)hb;
        g_w1L[(size_t)n * INP + k] = (unsigned short)bf16_bits(w - bf16_val(hb));
    }
}

// ---------------------------------------------------------------------------
// GEMM1 (tensor core, 3-term bf16 split): feats = relu(X @ W1 + b1)
// CTA: 64 batch x 128 hid, 256 threads (8 warps, warp = 16b x 64n)
// cp.async double-buffered K pipeline, KC=32, 25 chunks.
// ---------------------------------------------------------------------------
#define KSTR  20                 // u32 per k-row (16 data + 4 pad): conflict-free, 16B aligned
#define G_NC  (INP / 32)         // 25

#define G_OFF_BIAS 0
#define G_OFF_T    512
#define G_XSZ      (64 * KSTR * 4)     // 5120
#define G_WSZ      (128 * KSTR * 4)    // 10240
#define G_BUF      (2 * G_XSZ + 2 * G_WSZ)   // 30720
#define G_SMEM     (G_OFF_T + 2 * G_BUF)     // 61952

__global__ __launch_bounds__(256) void gemm1_mma_kernel(const float* __restrict__ b1) {
    extern __shared__ char smem[];
    float* sBias = (float*)(smem + G_OFF_BIAS);
    const uint32_t sb = smem_u32(smem);

    const int tid  = threadIdx.x;
    const int wid  = tid >> 5;
    const int lane = tid & 31;
    const int m0   = blockIdx.x * 64;

    if (tid < HID) sBias[tid] = b1[tid];

    const int wm  = wid >> 1;        // 0..3 : 16-batch tile
    const int wn  = wid & 1;         // 0..1 : 64-hid tile
    const int grp = lane >> 2;       // 0..7
    const int kp  = lane & 3;        // 0..3

    // issue cp.async for chunk c into buffer buf
    auto issue = [&](int c, int buf) {
        uint32_t base = sb + G_OFF_T + buf * G_BUF;
        {
            int b = tid >> 2, q = tid & 3;
            size_t go = (size_t)(m0 + b) * INP + c * 32 + q * 8;
            uint32_t so = (uint32_t)((b * KSTR + q * 4) * 4);
            cp16(base + so,          g_xH + go);
            cp16(base + G_XSZ + so,  g_xL + go);
        }
#pragma unroll
        for (int rep = 0; rep < 2; rep++) {
            int i = tid + rep * 256;
            int n = i >> 2, q = i & 3;
            size_t go = (size_t)n * INP + c * 32 + q * 8;
            uint32_t so = (uint32_t)((n * KSTR + q * 4) * 4);
            cp16(base + 2 * G_XSZ + so,          g_w1H + go);
            cp16(base + 2 * G_XSZ + G_WSZ + so,  g_w1L + go);
        }
    };

    float acc[8][4];
#pragma unroll
    for (int ni = 0; ni < 8; ni++)
#pragma unroll
        for (int r = 0; r < 4; r++) acc[ni][r] = 0.f;

    issue(0, 0);
    cp_commit();

    for (int c = 0; c < G_NC; c++) {
        cp_wait0();
        __syncthreads();
        if (c + 1 < G_NC) { issue(c + 1, (c + 1) & 1); cp_commit(); }

        const uint32_t* sXh = (const uint32_t*)(smem + G_OFF_T + (c & 1) * G_BUF);
        const uint32_t* sXl = sXh + 64 * KSTR;
        const uint32_t* sWh = sXl + 64 * KSTR;
        const uint32_t* sWl = sWh + 128 * KSTR;

#pragma unroll
        for (int s = 0; s < 2; s++) {
            const int rb = wm * 16;
            const int ko = s * 8 + kp;
            uint32_t ah0 = sXh[(rb + grp)     * KSTR + ko];
            uint32_t ah1 = sXh[(rb + grp + 8) * KSTR + ko];
            uint32_t ah2 = sXh[(rb + grp)     * KSTR + ko + 4];
            uint32_t ah3 = sXh[(rb + grp + 8) * KSTR + ko + 4];
            uint32_t al0 = sXl[(rb + grp)     * KSTR + ko];
            uint32_t al1 = sXl[(rb + grp + 8) * KSTR + ko];
            uint32_t al2 = sXl[(rb + grp)     * KSTR + ko + 4];
            uint32_t al3 = sXl[(rb + grp + 8) * KSTR + ko + 4];
#pragma unroll
            for (int ni = 0; ni < 8; ni++) {
                int nrow = wn * 64 + ni * 8 + grp;
                uint32_t bh0 = sWh[nrow * KSTR + ko];
                uint32_t bh1 = sWh[nrow * KSTR + ko + 4];
                mma16816(acc[ni], ah0, ah1, ah2, ah3, bh0, bh1);
                mma16816(acc[ni], al0, al1, al2, al3, bh0, bh1);
                uint32_t bl0 = sWl[nrow * KSTR + ko];
                uint32_t bl1 = sWl[nrow * KSTR + ko + 4];
                mma16816(acc[ni], ah0, ah1, ah2, ah3, bl0, bl1);
            }
        }
        __syncthreads();
    }

    // epilogue: bias + relu -> feats fp32 + bf16 hi/lo
    const int rowA = m0 + wm * 16 + grp;
#pragma unroll
    for (int ni = 0; ni < 8; ni++) {
        int col = wn * 64 + ni * 8 + kp * 2;
        float c0 = sBias[col], c1 = sBias[col + 1];
#pragma unroll
        for (int half = 0; half < 2; half++) {
            int row = rowA + half * 8;
            float v0 = acc[ni][2 * half]     + c0;
            float v1 = acc[ni][2 * half + 1] + c1;
            v0 = v0 > 0.f ? v0 : 0.f;
            v1 = v1 > 0.f ? v1 : 0.f;
            *(float2*)&g_feats[(size_t)row * HID + col] = make_float2(v0, v1);
            unsigned h0 = bf16_bits(v0), h1 = bf16_bits(v1);
            unsigned l0 = bf16_bits(v0 - bf16_val(h0));
            unsigned l1 = bf16_bits(v1 - bf16_val(h1));
            *(uint32_t*)&g_fH[(size_t)row * HID + col] = h0 | (h1 << 16);
            *(uint32_t*)&g_fL[(size_t)row * HID + col] = l0 | (l1 << 16);
        }
    }
}

// ---------------------------------------------------------------------------
// Prediction: pred = feats @ W2 + b2
// ---------------------------------------------------------------------------
__global__ __launch_bounds__(256) void pred_kernel(const float* __restrict__ W2,
                                                   const float* __restrict__ b2,
                                                   float* __restrict__ pred) {
    __shared__ float sF[64 * 132];
    __shared__ float sW2[HID * CLASS_NUM];
    const int tid = threadIdx.x;
    const int b0  = blockIdx.x * 64;
#pragma unroll
    for (int it = 0; it < 32; it++) {
        int e = it * 256 + tid;
        int r = e >> 7, d = e & 127;
        sF[r * 132 + d] = g_feats[(size_t)(b0 + r) * HID + d];
    }
    for (int e = tid; e < HID * CLASS_NUM; e += 256) sW2[e] = W2[e];
    __syncthreads();
    for (int o = tid; o < 64 * CLASS_NUM; o += 256) {
        int r = o / CLASS_NUM, c = o % CLASS_NUM;
        float s = b2[c];
#pragma unroll 8
        for (int d = 0; d < HID; d++) s += sF[r * 132 + d] * sW2[d * CLASS_NUM + c];
        pred[(size_t)(b0 + r) * CLASS_NUM + c] = s;
    }
}

// ---------------------------------------------------------------------------
// Tree kernel (mma.sync bf16, 3-term split, cp.async double-buffered):
//   per (tree, 64-batch tile): D[64b x 256n] -> sigmoid -> dec tile -> DFS
// ---------------------------------------------------------------------------
#define MB    64
#define DSTR  68
#define T_NC  (HID / 32)               // 4

#define T_OFF_DEC 0
#define T_OFF_NB  (256 * DSTR * 4)           // 69632
#define T_OFF_T   (T_OFF_NB + 256 * 4)       // 70656
#define T_FSZ     (64 * KSTR * 4)            // 5120
#define T_WSZ     (256 * KSTR * 4)           // 20480
#define T_BUF     (2 * T_FSZ + 2 * T_WSZ)    // 51200
#define TREE_SMEM (T_OFF_T + 2 * T_BUF)      // 173056

template <int LVL>
__device__ __forceinline__ void emit(float* __restrict__ outCol,
                                     const float* __restrict__ decCol,
                                     int node, float v) {
    outCol[(size_t)node * BATCH] = v;
    if constexpr (LVL < DEPTH - 1) {
        float d = decCol[node * DSTR];
        emit<LVL + 1>(outCol, decCol, 2 * node + 1, v * d);
        emit<LVL + 1>(outCol, decCol, 2 * node + 2, v * (1.f - d));
    }
}

__global__ __launch_bounds__(512) void tree_mma_kernel(const float* __restrict__ nodeb,
                                                       float* __restrict__ outAll) {
    extern __shared__ char smem[];
    float* decS = (float*)(smem + T_OFF_DEC);
    float* sNB  = (float*)(smem + T_OFF_NB);
    const uint32_t sb = smem_u32(smem);

    const int tid  = threadIdx.x;
    const int wid  = tid >> 5;
    const int lane = tid & 31;
    const int t    = blockIdx.y;
    const int b0   = blockIdx.x * MB;
    const size_t wbase = (size_t)t * 256 * HID;

    if (tid < 256)
        sNB[tid] = (tid < INTERNAL) ? nodeb[t * INTERNAL + tid] : 0.f;

    const int wb  = wid >> 2;
    const int wn  = wid & 3;
    const int grp = lane >> 2;
    const int kp  = lane & 3;

    auto issue = [&](int c, int buf) {
        uint32_t base = sb + T_OFF_T + buf * T_BUF;
        {
            int i = tid & 255, b = i >> 2, q = i & 3;
            size_t go = (size_t)(b0 + b) * HID + c * 32 + q * 8;
            uint32_t so = (uint32_t)((b * KSTR + q * 4) * 4);
            if (tid < 256) cp16(base + so,         g_fH + go);
            else           cp16(base + T_FSZ + so, g_fL + go);
        }
#pragma unroll
        for (int rep = 0; rep < 2; rep++) {
            int i = tid + rep * 512;
            int n = i >> 2, q = i & 3;
            size_t go = wbase + (size_t)n * HID + c * 32 + q * 8;
            uint32_t so = (uint32_t)((n * KSTR + q * 4) * 4);
            cp16(base + 2 * T_FSZ + so,          g_nwH + go);
            cp16(base + 2 * T_FSZ + T_WSZ + so,  g_nwL + go);
        }
    };

    float acc[8][4];
#pragma unroll
    for (int ni = 0; ni < 8; ni++)
#pragma unroll
        for (int r = 0; r < 4; r++) acc[ni][r] = 0.f;

    issue(0, 0);
    cp_commit();

    for (int c = 0; c < T_NC; c++) {
        cp_wait0();
        __syncthreads();
        if (c + 1 < T_NC) { issue(c + 1, (c + 1) & 1); cp_commit(); }

        const uint32_t* sFh = (const uint32_t*)(smem + T_OFF_T + (c & 1) * T_BUF);
        const uint32_t* sFl = sFh + 64 * KSTR;
        const uint32_t* sWh = sFl + 64 * KSTR;
        const uint32_t* sWl = sWh + 256 * KSTR;

#pragma unroll
        for (int s = 0; s < 2; s++) {
            const int rb = wb * 16;
            const int ko = s * 8 + kp;
            uint32_t ah0 = sFh[(rb + grp)     * KSTR + ko];
            uint32_t ah1 = sFh[(rb + grp + 8) * KSTR + ko];
            uint32_t ah2 = sFh[(rb + grp)     * KSTR + ko + 4];
            uint32_t ah3 = sFh[(rb + grp + 8) * KSTR + ko + 4];
            uint32_t al0 = sFl[(rb + grp)     * KSTR + ko];
            uint32_t al1 = sFl[(rb + grp + 8) * KSTR + ko];
            uint32_t al2 = sFl[(rb + grp)     * KSTR + ko + 4];
            uint32_t al3 = sFl[(rb + grp + 8) * KSTR + ko + 4];
#pragma unroll
            for (int ni = 0; ni < 8; ni++) {
                int nrow = wn * 64 + ni * 8 + grp;
                uint32_t bh0 = sWh[nrow * KSTR + ko];
                uint32_t bh1 = sWh[nrow * KSTR + ko + 4];
                mma16816(acc[ni], ah0, ah1, ah2, ah3, bh0, bh1);
                mma16816(acc[ni], al0, al1, al2, al3, bh0, bh1);
                uint32_t bl0 = sWl[nrow * KSTR + ko];
                uint32_t bl1 = sWl[nrow * KSTR + ko + 4];
                mma16816(acc[ni], ah0, ah1, ah2, ah3, bl0, bl1);
            }
        }
        __syncthreads();
    }

    // ---- epilogue: + bias, sigmoid -> dec tile ----
#pragma unroll
    for (int ni = 0; ni < 8; ni++) {
        int nbase = wn * 64 + ni * 8 + kp * 2;
        int bb    = wb * 16 + grp;
#pragma unroll
        for (int r = 0; r < 4; r++) {
            int node = nbase + (r & 1);
            int b    = bb + (r >> 1) * 8;
            if (node < INTERNAL)
                decS[node * DSTR + b] = sigmoidf_(acc[ni][r] + sNB[node]);
        }
    }
    __syncthreads();

    // ---- tree path products: 64 cols x 8 subtree threads ----
    {
        const int colb = tid & 63;
        const int q    = tid >> 6;
        float* outCol = outAll + (size_t)t * TOTAL * BATCH + (b0 + colb);
        const float* decCol = decS + colb;

        if (q < 7) {
            float v = 1.f; int x = q;
            while (x) {
                int p = (x - 1) >> 1;
                float d = decCol[p * DSTR];
                v *= (x == 2 * p + 1) ? d : (1.f - d);
                x = p;
            }
            outCol[(size_t)q * BATCH] = v;
        }

        const int rN = 7 + q;
        float v = 1.f; int x = rN;
        while (x) {
            int p = (x - 1) >> 1;
            float d = decCol[p * DSTR];
            v *= (x == 2 * p + 1) ? d : (1.f - d);
            x = p;
        }
        emit<3>(outCol, decCol, rN, v);
    }
}

// ---------------------------------------------------------------------------
extern "C" void kernel_launch(void* const* d_in, const int* in_sizes, int n_in,
                              void* d_out, int out_size) {
    const float* X     = (const float*)d_in[0];
    const float* W1    = (const float*)d_in[1];
    const float* b1    = (const float*)d_in[2];
    const float* W2    = (const float*)d_in[3];
    const float* b2    = (const float*)d_in[4];
    const float* nodeW = (const float*)d_in[5];
    const float* nodeb = (const float*)d_in[6];

    float* pred   = (float*)d_out;                               // [8192, 10]
    float* outAll = (float*)d_out + (size_t)BATCH * CLASS_NUM;   // [16, 511, 8192]

    cudaFuncSetAttribute(tree_mma_kernel, cudaFuncAttributeMaxDynamicSharedMemorySize,
                         TREE_SMEM);
    cudaFuncSetAttribute(gemm1_mma_kernel, cudaFuncAttributeMaxDynamicSharedMemorySize,
                         G_SMEM);

    conv_X_kernel<<<BATCH, 256>>>(X);
    conv_W1_kernel<<<HID, 256>>>(W1);
    conv_nodeW_kernel<<<TREES * 256 * HID / 256, 256>>>(nodeW);
    gemm1_mma_kernel<<<BATCH / 64, 256, G_SMEM>>>(b1);
    tree_mma_kernel<<<dim3(BATCH / MB, TREES), 512, TREE_SMEM>>>(nodeb, outAll);
    pred_kernel<<<BATCH / 64, 256>>>(W2, b2, pred);
}

// round 6
// speedup vs baseline: 1.8852x; 1.1303x over previous
#include <cuda_runtime.h>
#include <cuda_bf16.h>
#include <cstdint>

typedef unsigned long long u64;

#define BATCH     8192
#define IN_DIM    784
#define INP       800            // padded IN_DIM (multiple of 32)
#define HID       128
#define CLASS_NUM 10
#define TREES     16
#define INTERNAL  255
#define TOTAL     511
#define DEPTH     9

// ---------------- static scratch (no allocations) ---------------------------
__device__ float          g_feats[BATCH * HID];
__device__ unsigned short g_fH[BATCH * HID];
__device__ unsigned short g_fL[BATCH * HID];
__device__ unsigned short g_nwH[TREES * 256 * HID];
__device__ unsigned short g_nwL[TREES * 256 * HID];
__device__ unsigned short g_xH[BATCH * INP];
__device__ unsigned short g_xL[BATCH * INP];
__device__ unsigned short g_w1H[HID * INP];     // W1 transposed [hid][k]
__device__ unsigned short g_w1L[HID * INP];

// ---------------- helpers ----------------------------------------------------
__device__ __forceinline__ float sigmoidf_(float x) { return 1.f / (1.f + __expf(-x)); }

__device__ __forceinline__ unsigned bf16_bits(float x) {   // RNE
    uint32_t u = __float_as_uint(x);
    return (u + 0x7FFFu + ((u >> 16) & 1u)) >> 16;
}
__device__ __forceinline__ float bf16_val(unsigned bits) {
    return __uint_as_float(bits << 16);
}

__device__ __forceinline__ uint32_t smem_u32(const void* p) {
    uint32_t a;
    asm("{ .reg .u64 t; cvta.to.shared.u64 t, %1; cvt.u32.u64 %0, t; }" : "=r"(a) : "l"(p));
    return a;
}
__device__ __forceinline__ void cp16(uint32_t dst, const void* src) {
    asm volatile("cp.async.ca.shared.global [%0], [%1], 16;" :: "r"(dst), "l"(src));
}
__device__ __forceinline__ void cp_commit() {
    asm volatile("cp.async.commit_group;" ::: "memory");
}
__device__ __forceinline__ void cp_wait0() {
    asm volatile("cp.async.wait_group 0;" ::: "memory");
}

// warp-level bf16 MMA: D[16x8] += A[16x16] * B[16x8]  (fp32 accum)
__device__ __forceinline__ void mma16816(float* c, uint32_t a0, uint32_t a1,
                                         uint32_t a2, uint32_t a3,
                                         uint32_t b0, uint32_t b1) {
    asm volatile(
        "mma.sync.aligned.m16n8k16.row.col.f32.bf16.bf16.f32 "
        "{%0,%1,%2,%3}, {%4,%5,%6,%7}, {%8,%9}, {%0,%1,%2,%3};"
        : "+f"(c[0]), "+f"(c[1]), "+f"(c[2]), "+f"(c[3])
        : "r"(a0), "r"(a1), "r"(a2), "r"(a3), "r"(b0), "r"(b1));
}

// ---------------------------------------------------------------------------
// conversion kernels
// ---------------------------------------------------------------------------
__global__ __launch_bounds__(256) void conv_nodeW_kernel(const float* __restrict__ nodeW) {
    int idx  = blockIdx.x * 256 + threadIdx.x;
    int k    = idx & 127;
    int node = (idx >> 7) & 255;
    int t    = idx >> 15;
    float w  = (node < INTERNAL) ? nodeW[((size_t)t * INTERNAL + node) * HID + k] : 0.f;
    unsigned hb = bf16_bits(w);
    g_nwH[idx] = (unsigned short)hb;
    g_nwL[idx] = (unsigned short)bf16_bits(w - bf16_val(hb));
}

__global__ __launch_bounds__(256) void conv_X_kernel(const float* __restrict__ X) {
    int row = blockIdx.x;
    for (int k = threadIdx.x; k < INP; k += 256) {
        float x = (k < IN_DIM) ? X[(size_t)row * IN_DIM + k] : 0.f;
        unsigned hb = bf16_bits(x);
        g_xH[(size_t)row * INP + k] = (unsigned short)hb;
        g_xL[(size_t)row * INP + k] = (unsigned short)bf16_bits(x - bf16_val(hb));
    }
}

__global__ __launch_bounds__(256) void conv_W1_kernel(const float* __restrict__ W1) {
    int n = blockIdx.x;
    for (int k = threadIdx.x; k < INP; k += 256) {
        float w = (k < IN_DIM) ? W1[(size_t)k * HID + n] : 0.f;
        unsigned hb = bf16_bits(w);
        g_w1H[(size_t)n * INP + k] = (unsigned short)hb;
        g_w1L[(size_t)n * INP + k] = (unsigned short)bf16_bits(w - bf16_val(hb));
    }
}

// ---------------------------------------------------------------------------
// GEMM1 (tensor core, 3-term bf16 split): feats = relu(X @ W1 + b1)
// CTA: 32 batch x 128 hid, 128 threads (4 warps, warp = 16b x 64n), grid 256
// cp.async double-buffered K pipeline, KC=32, 25 chunks.
// ---------------------------------------------------------------------------
#define KSTR  20                 // u32 per k-row (16 data + 4 pad): conflict-free, 16B aligned
#define G_NC  (INP / 32)         // 25
#define G_MB  32

#define G_OFF_BIAS 0
#define G_OFF_T    512
#define G_XSZ      (G_MB * KSTR * 4)    // 2560
#define G_WSZ      (128 * KSTR * 4)     // 10240
#define G_BUF      (2 * G_XSZ + 2 * G_WSZ)   // 25600
#define G_SMEM     (G_OFF_T + 2 * G_BUF)     // 51712

__global__ __launch_bounds__(128, 2) void gemm1_mma_kernel(const float* __restrict__ b1) {
    extern __shared__ char smem[];
    float* sBias = (float*)(smem + G_OFF_BIAS);
    const uint32_t sb = smem_u32(smem);

    const int tid  = threadIdx.x;
    const int wid  = tid >> 5;
    const int lane = tid & 31;
    const int m0   = blockIdx.x * G_MB;

    if (tid < HID) sBias[tid] = b1[tid];

    const int wm  = wid >> 1;        // 0..1 : 16-batch tile
    const int wn  = wid & 1;         // 0..1 : 64-hid tile
    const int grp = lane >> 2;       // 0..7
    const int kp  = lane & 3;        // 0..3

    auto issue = [&](int c, int buf) {
        uint32_t base = sb + G_OFF_T + buf * G_BUF;
        {
            int b = tid >> 2, q = tid & 3;   // 32 rows x 4 quads = 128
            size_t go = (size_t)(m0 + b) * INP + c * 32 + q * 8;
            uint32_t so = (uint32_t)((b * KSTR + q * 4) * 4);
            cp16(base + so,          g_xH + go);
            cp16(base + G_XSZ + so,  g_xL + go);
        }
#pragma unroll
        for (int rep = 0; rep < 4; rep++) {  // 128 rows x 4 quads = 512
            int i = tid + rep * 128;
            int n = i >> 2, q = i & 3;
            size_t go = (size_t)n * INP + c * 32 + q * 8;
            uint32_t so = (uint32_t)((n * KSTR + q * 4) * 4);
            cp16(base + 2 * G_XSZ + so,          g_w1H + go);
            cp16(base + 2 * G_XSZ + G_WSZ + so,  g_w1L + go);
        }
    };

    float acc[8][4];
#pragma unroll
    for (int ni = 0; ni < 8; ni++)
#pragma unroll
        for (int r = 0; r < 4; r++) acc[ni][r] = 0.f;

    issue(0, 0);
    cp_commit();

    for (int c = 0; c < G_NC; c++) {
        cp_wait0();
        __syncthreads();
        if (c + 1 < G_NC) { issue(c + 1, (c + 1) & 1); cp_commit(); }

        const uint32_t* sXh = (const uint32_t*)(smem + G_OFF_T + (c & 1) * G_BUF);
        const uint32_t* sXl = sXh + G_MB * KSTR;
        const uint32_t* sWh = sXl + G_MB * KSTR;
        const uint32_t* sWl = sWh + 128 * KSTR;

#pragma unroll
        for (int s = 0; s < 2; s++) {
            const int rb = wm * 16;
            const int ko = s * 8 + kp;
            uint32_t ah0 = sXh[(rb + grp)     * KSTR + ko];
            uint32_t ah1 = sXh[(rb + grp + 8) * KSTR + ko];
            uint32_t ah2 = sXh[(rb + grp)     * KSTR + ko + 4];
            uint32_t ah3 = sXh[(rb + grp + 8) * KSTR + ko + 4];
            uint32_t al0 = sXl[(rb + grp)     * KSTR + ko];
            uint32_t al1 = sXl[(rb + grp + 8) * KSTR + ko];
            uint32_t al2 = sXl[(rb + grp)     * KSTR + ko + 4];
            uint32_t al3 = sXl[(rb + grp + 8) * KSTR + ko + 4];
#pragma unroll
            for (int ni = 0; ni < 8; ni++) {
                int nrow = wn * 64 + ni * 8 + grp;
                uint32_t bh0 = sWh[nrow * KSTR + ko];
                uint32_t bh1 = sWh[nrow * KSTR + ko + 4];
                mma16816(acc[ni], ah0, ah1, ah2, ah3, bh0, bh1);
                mma16816(acc[ni], al0, al1, al2, al3, bh0, bh1);
                uint32_t bl0 = sWl[nrow * KSTR + ko];
                uint32_t bl1 = sWl[nrow * KSTR + ko + 4];
                mma16816(acc[ni], ah0, ah1, ah2, ah3, bl0, bl1);
            }
        }
        __syncthreads();
    }

    // epilogue: bias + relu -> feats fp32 + bf16 hi/lo
    const int rowA = m0 + wm * 16 + grp;
#pragma unroll
    for (int ni = 0; ni < 8; ni++) {
        int col = wn * 64 + ni * 8 + kp * 2;
        float c0 = sBias[col], c1 = sBias[col + 1];
#pragma unroll
        for (int half = 0; half < 2; half++) {
            int row = rowA + half * 8;
            float v0 = acc[ni][2 * half]     + c0;
            float v1 = acc[ni][2 * half + 1] + c1;
            v0 = v0 > 0.f ? v0 : 0.f;
            v1 = v1 > 0.f ? v1 : 0.f;
            *(float2*)&g_feats[(size_t)row * HID + col] = make_float2(v0, v1);
            unsigned h0 = bf16_bits(v0), h1 = bf16_bits(v1);
            unsigned l0 = bf16_bits(v0 - bf16_val(h0));
            unsigned l1 = bf16_bits(v1 - bf16_val(h1));
            *(uint32_t*)&g_fH[(size_t)row * HID + col] = h0 | (h1 << 16);
            *(uint32_t*)&g_fL[(size_t)row * HID + col] = l0 | (l1 << 16);
        }
    }
}

// ---------------------------------------------------------------------------
// Prediction: pred = feats @ W2 + b2   (32 rows/block, grid 256)
// ---------------------------------------------------------------------------
__global__ __launch_bounds__(256) void pred_kernel(const float* __restrict__ W2,
                                                   const float* __restrict__ b2,
                                                   float* __restrict__ pred) {
    __shared__ float sF[32 * 132];
    __shared__ float sW2[HID * CLASS_NUM];
    const int tid = threadIdx.x;
    const int b0  = blockIdx.x * 32;
#pragma unroll
    for (int it = 0; it < 16; it++) {
        int e = it * 256 + tid;
        int r = e >> 7, d = e & 127;
        sF[r * 132 + d] = g_feats[(size_t)(b0 + r) * HID + d];
    }
    for (int e = tid; e < HID * CLASS_NUM; e += 256) sW2[e] = W2[e];
    __syncthreads();
    for (int o = tid; o < 32 * CLASS_NUM; o += 256) {
        int r = o / CLASS_NUM, c = o % CLASS_NUM;
        float s = b2[c];
#pragma unroll 8
        for (int d = 0; d < HID; d++) s += sF[r * 132 + d] * sW2[d * CLASS_NUM + c];
        pred[(size_t)(b0 + r) * CLASS_NUM + c] = s;
    }
}

// ---------------------------------------------------------------------------
// Tree kernel (mma.sync bf16, 3-term split, cp.async double-buffered):
//   per (tree, 64-batch tile): D[64b x 256n] -> sigmoid -> dec tile -> DFS
//   dec tile ALIASES the MMA tile buffers (live ranges disjoint) -> 2 CTAs/SM
// ---------------------------------------------------------------------------
#define MB    64
#define DSTR  68
#define T_NC  (HID / 32)               // 4

#define T_OFF_NB  0
#define T_OFF_T   1024
#define T_FSZ     (64 * KSTR * 4)            // 5120
#define T_WSZ     (256 * KSTR * 4)           // 20480
#define T_BUF     (2 * T_FSZ + 2 * T_WSZ)    // 51200
#define TREE_SMEM (T_OFF_T + 2 * T_BUF)      // 103424  (dec tile aliases T_OFF_T)

template <int LVL>
__device__ __forceinline__ void emit(float* __restrict__ outCol,
                                     const float* __restrict__ decCol,
                                     int node, float v) {
    outCol[(size_t)node * BATCH] = v;
    if constexpr (LVL < DEPTH - 1) {
        float d = decCol[node * DSTR];
        emit<LVL + 1>(outCol, decCol, 2 * node + 1, v * d);
        emit<LVL + 1>(outCol, decCol, 2 * node + 2, v * (1.f - d));
    }
}

__global__ __launch_bounds__(512, 2) void tree_mma_kernel(const float* __restrict__ nodeb,
                                                          float* __restrict__ outAll) {
    extern __shared__ char smem[];
    float* sNB  = (float*)(smem + T_OFF_NB);
    float* decS = (float*)(smem + T_OFF_T);   // aliases tile buffers (post-MMA)
    const uint32_t sb = smem_u32(smem);

    const int tid  = threadIdx.x;
    const int wid  = tid >> 5;
    const int lane = tid & 31;
    const int t    = blockIdx.y;
    const int b0   = blockIdx.x * MB;
    const size_t wbase = (size_t)t * 256 * HID;

    if (tid < 256)
        sNB[tid] = (tid < INTERNAL) ? nodeb[t * INTERNAL + tid] : 0.f;

    const int wb  = wid >> 2;
    const int wn  = wid & 3;
    const int grp = lane >> 2;
    const int kp  = lane & 3;

    auto issue = [&](int c, int buf) {
        uint32_t base = sb + T_OFF_T + buf * T_BUF;
        {
            int i = tid & 255, b = i >> 2, q = i & 3;
            size_t go = (size_t)(b0 + b) * HID + c * 32 + q * 8;
            uint32_t so = (uint32_t)((b * KSTR + q * 4) * 4);
            if (tid < 256) cp16(base + so,         g_fH + go);
            else           cp16(base + T_FSZ + so, g_fL + go);
        }
#pragma unroll
        for (int rep = 0; rep < 2; rep++) {
            int i = tid + rep * 512;
            int n = i >> 2, q = i & 3;
            size_t go = wbase + (size_t)n * HID + c * 32 + q * 8;
            uint32_t so = (uint32_t)((n * KSTR + q * 4) * 4);
            cp16(base + 2 * T_FSZ + so,          g_nwH + go);
            cp16(base + 2 * T_FSZ + T_WSZ + so,  g_nwL + go);
        }
    };

    float acc[8][4];
#pragma unroll
    for (int ni = 0; ni < 8; ni++)
#pragma unroll
        for (int r = 0; r < 4; r++) acc[ni][r] = 0.f;

    issue(0, 0);
    cp_commit();

    for (int c = 0; c < T_NC; c++) {
        cp_wait0();
        __syncthreads();
        if (c + 1 < T_NC) { issue(c + 1, (c + 1) & 1); cp_commit(); }

        const uint32_t* sFh = (const uint32_t*)(smem + T_OFF_T + (c & 1) * T_BUF);
        const uint32_t* sFl = sFh + 64 * KSTR;
        const uint32_t* sWh = sFl + 64 * KSTR;
        const uint32_t* sWl = sWh + 256 * KSTR;

#pragma unroll
        for (int s = 0; s < 2; s++) {
            const int rb = wb * 16;
            const int ko = s * 8 + kp;
            uint32_t ah0 = sFh[(rb + grp)     * KSTR + ko];
            uint32_t ah1 = sFh[(rb + grp + 8) * KSTR + ko];
            uint32_t ah2 = sFh[(rb + grp)     * KSTR + ko + 4];
            uint32_t ah3 = sFh[(rb + grp + 8) * KSTR + ko + 4];
            uint32_t al0 = sFl[(rb + grp)     * KSTR + ko];
            uint32_t al1 = sFl[(rb + grp + 8) * KSTR + ko];
            uint32_t al2 = sFl[(rb + grp)     * KSTR + ko + 4];
            uint32_t al3 = sFl[(rb + grp + 8) * KSTR + ko + 4];
#pragma unroll
            for (int ni = 0; ni < 8; ni++) {
                int nrow = wn * 64 + ni * 8 + grp;
                uint32_t bh0 = sWh[nrow * KSTR + ko];
                uint32_t bh1 = sWh[nrow * KSTR + ko + 4];
                mma16816(acc[ni], ah0, ah1, ah2, ah3, bh0, bh1);
                mma16816(acc[ni], al0, al1, al2, al3, bh0, bh1);
                uint32_t bl0 = sWl[nrow * KSTR + ko];
                uint32_t bl1 = sWl[nrow * KSTR + ko + 4];
                mma16816(acc[ni], ah0, ah1, ah2, ah3, bl0, bl1);
            }
        }
        __syncthreads();
    }

    // ---- epilogue: + bias, sigmoid -> dec tile (aliases dead MMA buffers) ----
#pragma unroll
    for (int ni = 0; ni < 8; ni++) {
        int nbase = wn * 64 + ni * 8 + kp * 2;
        int bb    = wb * 16 + grp;
#pragma unroll
        for (int r = 0; r < 4; r++) {
            int node = nbase + (r & 1);
            int b    = bb + (r >> 1) * 8;
            if (node < INTERNAL)
                decS[node * DSTR + b] = sigmoidf_(acc[ni][r] + sNB[node]);
        }
    }
    __syncthreads();

    // ---- tree path products: 64 cols x 8 subtree threads ----
    {
        const int colb = tid & 63;
        const int q    = tid >> 6;
        float* outCol = outAll + (size_t)t * TOTAL * BATCH + (b0 + colb);
        const float* decCol = decS + colb;

        if (q < 7) {
            float v = 1.f; int x = q;
            while (x) {
                int p = (x - 1) >> 1;
                float d = decCol[p * DSTR];
                v *= (x == 2 * p + 1) ? d : (1.f - d);
                x = p;
            }
            outCol[(size_t)q * BATCH] = v;
        }

        const int rN = 7 + q;
        float v = 1.f; int x = rN;
        while (x) {
            int p = (x - 1) >> 1;
            float d = decCol[p * DSTR];
            v *= (x == 2 * p + 1) ? d : (1.f - d);
            x = p;
        }
        emit<3>(outCol, decCol, rN, v);
    }
}

// ---------------------------------------------------------------------------
extern "C" void kernel_launch(void* const* d_in, const int* in_sizes, int n_in,
                              void* d_out, int out_size) {
    const float* X     = (const float*)d_in[0];
    const float* W1    = (const float*)d_in[1];
    const float* b1    = (const float*)d_in[2];
    const float* W2    = (const float*)d_in[3];
    const float* b2    = (const float*)d_in[4];
    const float* nodeW = (const float*)d_in[5];
    const float* nodeb = (const float*)d_in[6];

    float* pred   = (float*)d_out;                               // [8192, 10]
    float* outAll = (float*)d_out + (size_t)BATCH * CLASS_NUM;   // [16, 511, 8192]

    cudaFuncSetAttribute(tree_mma_kernel, cudaFuncAttributeMaxDynamicSharedMemorySize,
                         TREE_SMEM);
    cudaFuncSetAttribute(gemm1_mma_kernel, cudaFuncAttributeMaxDynamicSharedMemorySize,
                         G_SMEM);

    conv_X_kernel<<<BATCH, 256>>>(X);
    conv_W1_kernel<<<HID, 256>>>(W1);
    conv_nodeW_kernel<<<TREES * 256 * HID / 256, 256>>>(nodeW);
    gemm1_mma_kernel<<<BATCH / G_MB, 128, G_SMEM>>>(b1);
    tree_mma_kernel<<<dim3(BATCH / MB, TREES), 512, TREE_SMEM>>>(nodeb, outAll);
    pred_kernel<<<BATCH / 32, 256>>>(W2, b2, pred);
}

// round 7
// speedup vs baseline: 2.0005x; 1.0612x over previous
#include <cuda_runtime.h>
#include <cuda_bf16.h>
#include <cstdint>

typedef unsigned long long u64;

#define BATCH     8192
#define IN_DIM    784
#define INP       800            // padded IN_DIM (multiple of 32)
#define HID       128
#define CLASS_NUM 10
#define TREES     16
#define INTERNAL  255
#define TOTAL     511
#define DEPTH     9

// ---------------- static scratch (no allocations) ---------------------------
__device__ float          g_feats[BATCH * HID];
__device__ unsigned short g_fH[BATCH * HID];
__device__ unsigned short g_fL[BATCH * HID];
__device__ unsigned short g_nwH[TREES * 256 * HID];
__device__ unsigned short g_nwL[TREES * 256 * HID];
__device__ unsigned short g_xH[BATCH * INP];
__device__ unsigned short g_xL[BATCH * INP];
__device__ unsigned short g_w1H[HID * INP];     // W1 transposed [hid][k]
__device__ unsigned short g_w1L[HID * INP];

// ---------------- helpers ----------------------------------------------------
__device__ __forceinline__ float sigmoidf_(float x) { return 1.f / (1.f + __expf(-x)); }

__device__ __forceinline__ unsigned bf16_bits(float x) {   // RNE
    uint32_t u = __float_as_uint(x);
    return (u + 0x7FFFu + ((u >> 16) & 1u)) >> 16;
}
__device__ __forceinline__ float bf16_val(unsigned bits) {
    return __uint_as_float(bits << 16);
}

__device__ __forceinline__ uint32_t smem_u32(const void* p) {
    uint32_t a;
    asm("{ .reg .u64 t; cvta.to.shared.u64 t, %1; cvt.u32.u64 %0, t; }" : "=r"(a) : "l"(p));
    return a;
}
__device__ __forceinline__ void cp16(uint32_t dst, const void* src) {
    asm volatile("cp.async.ca.shared.global [%0], [%1], 16;" :: "r"(dst), "l"(src));
}
__device__ __forceinline__ void cp_commit() {
    asm volatile("cp.async.commit_group;" ::: "memory");
}
__device__ __forceinline__ void cp_wait0() {
    asm volatile("cp.async.wait_group 0;" ::: "memory");
}

// ldmatrix x4: four 8x8 b16 matrices, lane L supplies row address
__device__ __forceinline__ void ldsm4(uint32_t& r0, uint32_t& r1, uint32_t& r2,
                                      uint32_t& r3, uint32_t addr) {
    asm volatile("ldmatrix.sync.aligned.m8n8.x4.shared.b16 {%0,%1,%2,%3}, [%4];"
                 : "=r"(r0), "=r"(r1), "=r"(r2), "=r"(r3) : "r"(addr));
}

// warp-level bf16 MMA: D[16x8] += A[16x16] * B[16x8]  (fp32 accum)
__device__ __forceinline__ void mma16816(float* c, uint32_t a0, uint32_t a1,
                                         uint32_t a2, uint32_t a3,
                                         uint32_t b0, uint32_t b1) {
    asm volatile(
        "mma.sync.aligned.m16n8k16.row.col.f32.bf16.bf16.f32 "
        "{%0,%1,%2,%3}, {%4,%5,%6,%7}, {%8,%9}, {%0,%1,%2,%3};"
        : "+f"(c[0]), "+f"(c[1]), "+f"(c[2]), "+f"(c[3])
        : "r"(a0), "r"(a1), "r"(a2), "r"(a3), "r"(b0), "r"(b1));
}

// ---------------------------------------------------------------------------
// conversion kernels
// ---------------------------------------------------------------------------
__global__ __launch_bounds__(256) void conv_nodeW_kernel(const float* __restrict__ nodeW) {
    int idx  = blockIdx.x * 256 + threadIdx.x;
    int k    = idx & 127;
    int node = (idx >> 7) & 255;
    int t    = idx >> 15;
    float w  = (node < INTERNAL) ? nodeW[((size_t)t * INTERNAL + node) * HID + k] : 0.f;
    unsigned hb = bf16_bits(w);
    g_nwH[idx] = (unsigned short)hb;
    g_nwL[idx] = (unsigned short)bf16_bits(w - bf16_val(hb));
}

__global__ __launch_bounds__(256) void conv_X_kernel(const float* __restrict__ X) {
    int row = blockIdx.x;
    for (int k = threadIdx.x; k < INP; k += 256) {
        float x = (k < IN_DIM) ? X[(size_t)row * IN_DIM + k] : 0.f;
        unsigned hb = bf16_bits(x);
        g_xH[(size_t)row * INP + k] = (unsigned short)hb;
        g_xL[(size_t)row * INP + k] = (unsigned short)bf16_bits(x - bf16_val(hb));
    }
}

__global__ __launch_bounds__(256) void conv_W1_kernel(const float* __restrict__ W1) {
    int n = blockIdx.x;
    for (int k = threadIdx.x; k < INP; k += 256) {
        float w = (k < IN_DIM) ? W1[(size_t)k * HID + n] : 0.f;
        unsigned hb = bf16_bits(w);
        g_w1H[(size_t)n * INP + k] = (unsigned short)hb;
        g_w1L[(size_t)n * INP + k] = (unsigned short)bf16_bits(w - bf16_val(hb));
    }
}

// ---------------------------------------------------------------------------
// GEMM1 (tensor core, 3-term bf16 split): feats = relu(X @ W1 + b1)
// CTA: 64 batch x 128 hid, 256 threads (8 warps, warp = 16b x 64n), grid 128
// ---------------------------------------------------------------------------
#define KSTR  20                 // u32 per k-row: conflict-free, 16B aligned
#define G_NC  (INP / 32)         // 25
#define G_MB  64

#define G_OFF_BIAS 0
#define G_OFF_T    512
#define G_XSZ      (G_MB * KSTR * 4)    // 5120
#define G_WSZ      (128 * KSTR * 4)     // 10240
#define G_BUF      (2 * G_XSZ + 2 * G_WSZ)   // 30720
#define G_SMEM     (G_OFF_T + 2 * G_BUF)     // 61952

__global__ __launch_bounds__(256) void gemm1_mma_kernel(const float* __restrict__ b1) {
    extern __shared__ char smem[];
    float* sBias = (float*)(smem + G_OFF_BIAS);
    const uint32_t sb = smem_u32(smem);

    const int tid  = threadIdx.x;
    const int wid  = tid >> 5;
    const int lane = tid & 31;
    const int m0   = blockIdx.x * G_MB;

    if (tid < HID) sBias[tid] = b1[tid];

    const int wm  = wid >> 1;        // 0..3 : 16-batch tile
    const int wn  = wid & 1;         // 0..1 : 64-hid tile
    const int grp = lane >> 2;       // 0..7
    const int kp  = lane & 3;        // 0..3

    // ldmatrix per-lane byte offsets
    const int lrow = lane & 15;
    const int lcol = (lane >> 4) * 4;     // u32: +4 => k+8
    const uint32_t aOff = (uint32_t)(((wm * 16 + lrow) * KSTR + lcol) * 4);
    uint32_t bOff[4];
#pragma unroll
    for (int pi = 0; pi < 4; pi++)
        bOff[pi] = (uint32_t)(((wn * 64 + pi * 16 + lrow) * KSTR + lcol) * 4);

    auto issue = [&](int c, int buf) {
        uint32_t base = sb + G_OFF_T + buf * G_BUF;
        {
            int b = tid >> 2, q = tid & 3;   // 64 x 4 = 256
            size_t go = (size_t)(m0 + b) * INP + c * 32 + q * 8;
            uint32_t so = (uint32_t)((b * KSTR + q * 4) * 4);
            cp16(base + so,          g_xH + go);
            cp16(base + G_XSZ + so,  g_xL + go);
        }
#pragma unroll
        for (int rep = 0; rep < 2; rep++) {  // 128 x 4 = 512
            int i = tid + rep * 256;
            int n = i >> 2, q = i & 3;
            size_t go = (size_t)n * INP + c * 32 + q * 8;
            uint32_t so = (uint32_t)((n * KSTR + q * 4) * 4);
            cp16(base + 2 * G_XSZ + so,          g_w1H + go);
            cp16(base + 2 * G_XSZ + G_WSZ + so,  g_w1L + go);
        }
    };

    float acc[8][4];
#pragma unroll
    for (int ni = 0; ni < 8; ni++)
#pragma unroll
        for (int r = 0; r < 4; r++) acc[ni][r] = 0.f;

    issue(0, 0);
    cp_commit();

    for (int c = 0; c < G_NC; c++) {
        cp_wait0();
        __syncthreads();
        if (c + 1 < G_NC) { issue(c + 1, (c + 1) & 1); cp_commit(); }

        uint32_t xhB = sb + G_OFF_T + (c & 1) * G_BUF;
        uint32_t xlB = xhB + G_XSZ;
        uint32_t whB = xlB + G_XSZ;
        uint32_t wlB = whB + G_WSZ;

#pragma unroll
        for (int s = 0; s < 2; s++) {
            uint32_t sB = s * 32;
            uint32_t ah0, ah1, ah2, ah3, al0, al1, al2, al3;
            ldsm4(ah0, ah1, ah2, ah3, xhB + aOff + sB);
            ldsm4(al0, al1, al2, al3, xlB + aOff + sB);
#pragma unroll
            for (int pi = 0; pi < 4; pi++) {
                uint32_t h0, h1, h2, h3, l0, l1, l2, l3;
                ldsm4(h0, h1, h2, h3, whB + bOff[pi] + sB);
                ldsm4(l0, l1, l2, l3, wlB + bOff[pi] + sB);
                mma16816(acc[2 * pi],     ah0, ah1, ah2, ah3, h0, h2);
                mma16816(acc[2 * pi],     al0, al1, al2, al3, h0, h2);
                mma16816(acc[2 * pi],     ah0, ah1, ah2, ah3, l0, l2);
                mma16816(acc[2 * pi + 1], ah0, ah1, ah2, ah3, h1, h3);
                mma16816(acc[2 * pi + 1], al0, al1, al2, al3, h1, h3);
                mma16816(acc[2 * pi + 1], ah0, ah1, ah2, ah3, l1, l3);
            }
        }
    }

    // epilogue: bias + relu -> feats fp32 + bf16 hi/lo
    const int rowA = m0 + wm * 16 + grp;
#pragma unroll
    for (int ni = 0; ni < 8; ni++) {
        int col = wn * 64 + ni * 8 + kp * 2;
        float c0 = sBias[col], c1 = sBias[col + 1];
#pragma unroll
        for (int half = 0; half < 2; half++) {
            int row = rowA + half * 8;
            float v0 = acc[ni][2 * half]     + c0;
            float v1 = acc[ni][2 * half + 1] + c1;
            v0 = v0 > 0.f ? v0 : 0.f;
            v1 = v1 > 0.f ? v1 : 0.f;
            *(float2*)&g_feats[(size_t)row * HID + col] = make_float2(v0, v1);
            unsigned h0 = bf16_bits(v0), h1 = bf16_bits(v1);
            unsigned l0 = bf16_bits(v0 - bf16_val(h0));
            unsigned l1 = bf16_bits(v1 - bf16_val(h1));
            *(uint32_t*)&g_fH[(size_t)row * HID + col] = h0 | (h1 << 16);
            *(uint32_t*)&g_fL[(size_t)row * HID + col] = l0 | (l1 << 16);
        }
    }
}

// ---------------------------------------------------------------------------
// Prediction: pred = feats @ W2 + b2   (32 rows/block, grid 256)
// ---------------------------------------------------------------------------
__global__ __launch_bounds__(256) void pred_kernel(const float* __restrict__ W2,
                                                   const float* __restrict__ b2,
                                                   float* __restrict__ pred) {
    __shared__ float sF[32 * 132];
    __shared__ float sW2[HID * CLASS_NUM];
    const int tid = threadIdx.x;
    const int b0  = blockIdx.x * 32;
#pragma unroll
    for (int it = 0; it < 16; it++) {
        int e = it * 256 + tid;
        int r = e >> 7, d = e & 127;
        sF[r * 132 + d] = g_feats[(size_t)(b0 + r) * HID + d];
    }
    for (int e = tid; e < HID * CLASS_NUM; e += 256) sW2[e] = W2[e];
    __syncthreads();
    for (int o = tid; o < 32 * CLASS_NUM; o += 256) {
        int r = o / CLASS_NUM, c = o % CLASS_NUM;
        float s = b2[c];
#pragma unroll 8
        for (int d = 0; d < HID; d++) s += sF[r * 132 + d] * sW2[d * CLASS_NUM + c];
        pred[(size_t)(b0 + r) * CLASS_NUM + c] = s;
    }
}

// ---------------------------------------------------------------------------
// Tree kernel (mma.sync bf16, 3-term split, ldmatrix, cp.async dbuf):
//   per (tree, 64-batch tile): D[64b x 256n] -> sigmoid -> dec tile -> DFS
//   dec tile ALIASES the MMA tile buffers -> 2 CTAs/SM
// ---------------------------------------------------------------------------
#define MB    64
#define DSTR  68
#define T_NC  (HID / 32)               // 4

#define T_OFF_NB  0
#define T_OFF_T   1024
#define T_FSZ     (64 * KSTR * 4)            // 5120
#define T_WSZ     (256 * KSTR * 4)           // 20480
#define T_BUF     (2 * T_FSZ + 2 * T_WSZ)    // 51200
#define TREE_SMEM (T_OFF_T + 2 * T_BUF)      // 103424

template <int LVL>
__device__ __forceinline__ void emit(float* __restrict__ outCol,
                                     const float* __restrict__ decCol,
                                     int node, float v) {
    outCol[(size_t)node * BATCH] = v;
    if constexpr (LVL < DEPTH - 1) {
        float d = decCol[node * DSTR];
        emit<LVL + 1>(outCol, decCol, 2 * node + 1, v * d);
        emit<LVL + 1>(outCol, decCol, 2 * node + 2, v * (1.f - d));
    }
}

__global__ __launch_bounds__(512, 2) void tree_mma_kernel(const float* __restrict__ nodeb,
                                                          float* __restrict__ outAll) {
    extern __shared__ char smem[];
    float* sNB  = (float*)(smem + T_OFF_NB);
    float* decS = (float*)(smem + T_OFF_T);   // aliases tile buffers (post-MMA)
    const uint32_t sb = smem_u32(smem);

    const int tid  = threadIdx.x;
    const int wid  = tid >> 5;
    const int lane = tid & 31;
    const int t    = blockIdx.y;
    const int b0   = blockIdx.x * MB;
    const size_t wbase = (size_t)t * 256 * HID;

    if (tid < 256)
        sNB[tid] = (tid < INTERNAL) ? nodeb[t * INTERNAL + tid] : 0.f;

    const int wb  = wid >> 2;      // 0..3: 16-batch tile
    const int wn  = wid & 3;       // 0..3: 64-node tile
    const int grp = lane >> 2;
    const int kp  = lane & 3;

    const int lrow = lane & 15;
    const int lcol = (lane >> 4) * 4;
    const uint32_t aOff = (uint32_t)(((wb * 16 + lrow) * KSTR + lcol) * 4);
    uint32_t bOff[4];
#pragma unroll
    for (int pi = 0; pi < 4; pi++)
        bOff[pi] = (uint32_t)(((wn * 64 + pi * 16 + lrow) * KSTR + lcol) * 4);

    auto issue = [&](int c, int buf) {
        uint32_t base = sb + T_OFF_T + buf * T_BUF;
        {
            int i = tid & 255, b = i >> 2, q = i & 3;
            size_t go = (size_t)(b0 + b) * HID + c * 32 + q * 8;
            uint32_t so = (uint32_t)((b * KSTR + q * 4) * 4);
            if (tid < 256) cp16(base + so,         g_fH + go);
            else           cp16(base + T_FSZ + so, g_fL + go);
        }
#pragma unroll
        for (int rep = 0; rep < 2; rep++) {
            int i = tid + rep * 512;
            int n = i >> 2, q = i & 3;
            size_t go = wbase + (size_t)n * HID + c * 32 + q * 8;
            uint32_t so = (uint32_t)((n * KSTR + q * 4) * 4);
            cp16(base + 2 * T_FSZ + so,          g_nwH + go);
            cp16(base + 2 * T_FSZ + T_WSZ + so,  g_nwL + go);
        }
    };

    float acc[8][4];
#pragma unroll
    for (int ni = 0; ni < 8; ni++)
#pragma unroll
        for (int r = 0; r < 4; r++) acc[ni][r] = 0.f;

    issue(0, 0);
    cp_commit();

    for (int c = 0; c < T_NC; c++) {
        cp_wait0();
        __syncthreads();
        if (c + 1 < T_NC) { issue(c + 1, (c + 1) & 1); cp_commit(); }

        uint32_t fhB = sb + T_OFF_T + (c & 1) * T_BUF;
        uint32_t flB = fhB + T_FSZ;
        uint32_t whB = flB + T_FSZ;
        uint32_t wlB = whB + T_WSZ;

#pragma unroll
        for (int s = 0; s < 2; s++) {
            uint32_t sB = s * 32;
            uint32_t ah0, ah1, ah2, ah3, al0, al1, al2, al3;
            ldsm4(ah0, ah1, ah2, ah3, fhB + aOff + sB);
            ldsm4(al0, al1, al2, al3, flB + aOff + sB);
#pragma unroll
            for (int pi = 0; pi < 4; pi++) {
                uint32_t h0, h1, h2, h3, l0, l1, l2, l3;
                ldsm4(h0, h1, h2, h3, whB + bOff[pi] + sB);
                ldsm4(l0, l1, l2, l3, wlB + bOff[pi] + sB);
                mma16816(acc[2 * pi],     ah0, ah1, ah2, ah3, h0, h2);
                mma16816(acc[2 * pi],     al0, al1, al2, al3, h0, h2);
                mma16816(acc[2 * pi],     ah0, ah1, ah2, ah3, l0, l2);
                mma16816(acc[2 * pi + 1], ah0, ah1, ah2, ah3, h1, h3);
                mma16816(acc[2 * pi + 1], al0, al1, al2, al3, h1, h3);
                mma16816(acc[2 * pi + 1], ah0, ah1, ah2, ah3, l1, l3);
            }
        }
    }

    // dec tile aliases the MMA buffers: all compute must be done first
    __syncthreads();

    // ---- epilogue: + bias, sigmoid -> dec tile ----
#pragma unroll
    for (int ni = 0; ni < 8; ni++) {
        int nbase = wn * 64 + ni * 8 + kp * 2;
        int bb    = wb * 16 + grp;
#pragma unroll
        for (int r = 0; r < 4; r++) {
            int node = nbase + (r & 1);
            int b    = bb + (r >> 1) * 8;
            if (node < INTERNAL)
                decS[node * DSTR + b] = sigmoidf_(acc[ni][r] + sNB[node]);
        }
    }
    __syncthreads();

    // ---- tree path products: 64 cols x 8 subtree threads ----
    {
        const int colb = tid & 63;
        const int q    = tid >> 6;
        float* outCol = outAll + (size_t)t * TOTAL * BATCH + (b0 + colb);
        const float* decCol = decS + colb;

        if (q < 7) {
            float v = 1.f; int x = q;
            while (x) {
                int p = (x - 1) >> 1;
                float d = decCol[p * DSTR];
                v *= (x == 2 * p + 1) ? d : (1.f - d);
                x = p;
            }
            outCol[(size_t)q * BATCH] = v;
        }

        const int rN = 7 + q;
        float v = 1.f; int x = rN;
        while (x) {
            int p = (x - 1) >> 1;
            float d = decCol[p * DSTR];
            v *= (x == 2 * p + 1) ? d : (1.f - d);
            x = p;
        }
        emit<3>(outCol, decCol, rN, v);
    }
}

// ---------------------------------------------------------------------------
extern "C" void kernel_launch(void* const* d_in, const int* in_sizes, int n_in,
                              void* d_out, int out_size) {
    const float* X     = (const float*)d_in[0];
    const float* W1    = (const float*)d_in[1];
    const float* b1    = (const float*)d_in[2];
    const float* W2    = (const float*)d_in[3];
    const float* b2    = (const float*)d_in[4];
    const float* nodeW = (const float*)d_in[5];
    const float* nodeb = (const float*)d_in[6];

    float* pred   = (float*)d_out;                               // [8192, 10]
    float* outAll = (float*)d_out + (size_t)BATCH * CLASS_NUM;   // [16, 511, 8192]

    cudaFuncSetAttribute(tree_mma_kernel, cudaFuncAttributeMaxDynamicSharedMemorySize,
                         TREE_SMEM);
    cudaFuncSetAttribute(gemm1_mma_kernel, cudaFuncAttributeMaxDynamicSharedMemorySize,
                         G_SMEM);

    conv_X_kernel<<<BATCH, 256>>>(X);
    conv_W1_kernel<<<HID, 256>>>(W1);
    conv_nodeW_kernel<<<TREES * 256 * HID / 256, 256>>>(nodeW);
    gemm1_mma_kernel<<<BATCH / G_MB, 256, G_SMEM>>>(b1);
    tree_mma_kernel<<<dim3(BATCH / MB, TREES), 512, TREE_SMEM>>>(nodeb, outAll);
    pred_kernel<<<BATCH / 32, 256>>>(W2, b2, pred);
}

// round 8
// speedup vs baseline: 2.2265x; 1.1130x over previous
#include <cuda_runtime.h>
#include <cuda_bf16.h>
#include <cstdint>

typedef unsigned long long u64;

#define BATCH     8192
#define IN_DIM    784
#define INP       800            // padded IN_DIM (multiple of 32)
#define HID       128
#define CLASS_NUM 10
#define TREES     16
#define INTERNAL  255
#define TOTAL     511
#define DEPTH     9

// ---------------- static scratch (no allocations) ---------------------------
__device__ float          g_feats[BATCH * HID];
__device__ unsigned short g_fH[BATCH * HID];
__device__ unsigned short g_fL[BATCH * HID];
__device__ unsigned short g_nwH[TREES * 256 * HID];
__device__ unsigned short g_nwL[TREES * 256 * HID];
__device__ unsigned short g_xH[BATCH * INP];
__device__ unsigned short g_xL[BATCH * INP];
__device__ unsigned short g_w1H[HID * INP];     // W1 transposed [hid][k]
__device__ unsigned short g_w1L[HID * INP];

// ---------------- helpers ----------------------------------------------------
__device__ __forceinline__ float sigmoidf_(float x) { return 1.f / (1.f + __expf(-x)); }

__device__ __forceinline__ unsigned bf16_bits(float x) {   // RNE
    uint32_t u = __float_as_uint(x);
    return (u + 0x7FFFu + ((u >> 16) & 1u)) >> 16;
}
__device__ __forceinline__ float bf16_val(unsigned bits) {
    return __uint_as_float(bits << 16);
}

__device__ __forceinline__ uint32_t smem_u32(const void* p) {
    uint32_t a;
    asm("{ .reg .u64 t; cvta.to.shared.u64 t, %1; cvt.u32.u64 %0, t; }" : "=r"(a) : "l"(p));
    return a;
}
__device__ __forceinline__ void cp16(uint32_t dst, const void* src) {
    asm volatile("cp.async.cg.shared.global [%0], [%1], 16;" :: "r"(dst), "l"(src));
}
__device__ __forceinline__ void cp_commit() {
    asm volatile("cp.async.commit_group;" ::: "memory");
}
__device__ __forceinline__ void cp_wait0() {
    asm volatile("cp.async.wait_group 0;" ::: "memory");
}
__device__ __forceinline__ void stcs2(float* p, float2 v) {
    asm volatile("st.global.cs.v2.f32 [%0], {%1, %2};" :: "l"(p), "f"(v.x), "f"(v.y)
                 : "memory");
}

// ldmatrix x4: four 8x8 b16 matrices, lane L supplies row address
__device__ __forceinline__ void ldsm4(uint32_t& r0, uint32_t& r1, uint32_t& r2,
                                      uint32_t& r3, uint32_t addr) {
    asm volatile("ldmatrix.sync.aligned.m8n8.x4.shared.b16 {%0,%1,%2,%3}, [%4];"
                 : "=r"(r0), "=r"(r1), "=r"(r2), "=r"(r3) : "r"(addr));
}

// warp-level bf16 MMA: D[16x8] += A[16x16] * B[16x8]  (fp32 accum)
__device__ __forceinline__ void mma16816(float* c, uint32_t a0, uint32_t a1,
                                         uint32_t a2, uint32_t a3,
                                         uint32_t b0, uint32_t b1) {
    asm volatile(
        "mma.sync.aligned.m16n8k16.row.col.f32.bf16.bf16.f32 "
        "{%0,%1,%2,%3}, {%4,%5,%6,%7}, {%8,%9}, {%0,%1,%2,%3};"
        : "+f"(c[0]), "+f"(c[1]), "+f"(c[2]), "+f"(c[3])
        : "r"(a0), "r"(a1), "r"(a2), "r"(a3), "r"(b0), "r"(b1));
}

// ---------------------------------------------------------------------------
// conversion kernels
// ---------------------------------------------------------------------------
__global__ __launch_bounds__(256) void conv_nodeW_kernel(const float* __restrict__ nodeW) {
    int idx  = blockIdx.x * 256 + threadIdx.x;
    int k    = idx & 127;
    int node = (idx >> 7) & 255;
    int t    = idx >> 15;
    float w  = (node < INTERNAL) ? nodeW[((size_t)t * INTERNAL + node) * HID + k] : 0.f;
    unsigned hb = bf16_bits(w);
    g_nwH[idx] = (unsigned short)hb;
    g_nwL[idx] = (unsigned short)bf16_bits(w - bf16_val(hb));
}

__global__ __launch_bounds__(256) void conv_X_kernel(const float* __restrict__ X) {
    int row = blockIdx.x;
    for (int k = threadIdx.x; k < INP; k += 256) {
        float x = (k < IN_DIM) ? X[(size_t)row * IN_DIM + k] : 0.f;
        unsigned hb = bf16_bits(x);
        g_xH[(size_t)row * INP + k] = (unsigned short)hb;
        g_xL[(size_t)row * INP + k] = (unsigned short)bf16_bits(x - bf16_val(hb));
    }
}

__global__ __launch_bounds__(256) void conv_W1_kernel(const float* __restrict__ W1) {
    int n = blockIdx.x;
    for (int k = threadIdx.x; k < INP; k += 256) {
        float w = (k < IN_DIM) ? W1[(size_t)k * HID + n] : 0.f;
        unsigned hb = bf16_bits(w);
        g_w1H[(size_t)n * INP + k] = (unsigned short)hb;
        g_w1L[(size_t)n * INP + k] = (unsigned short)bf16_bits(w - bf16_val(hb));
    }
}

// ---------------------------------------------------------------------------
// GEMM1 (tensor core, 3-term bf16 split): feats = relu(X @ W1 + b1)
// CTA: 64 batch x 128 hid, 256 threads (8 warps, warp = 16b x 64n), grid 128
// ---------------------------------------------------------------------------
#define KSTR  20                 // u32 per k-row: conflict-free, 16B aligned
#define G_NC  (INP / 32)         // 25
#define G_MB  64

#define G_OFF_BIAS 0
#define G_OFF_T    512
#define G_XSZ      (G_MB * KSTR * 4)    // 5120
#define G_WSZ      (128 * KSTR * 4)     // 10240
#define G_BUF      (2 * G_XSZ + 2 * G_WSZ)   // 30720
#define G_SMEM     (G_OFF_T + 2 * G_BUF)     // 61952

__global__ __launch_bounds__(256) void gemm1_mma_kernel(const float* __restrict__ b1) {
    extern __shared__ char smem[];
    float* sBias = (float*)(smem + G_OFF_BIAS);
    const uint32_t sb = smem_u32(smem);

    const int tid  = threadIdx.x;
    const int wid  = tid >> 5;
    const int lane = tid & 31;
    const int m0   = blockIdx.x * G_MB;

    if (tid < HID) sBias[tid] = b1[tid];

    const int wm  = wid >> 1;        // 0..3 : 16-batch tile
    const int wn  = wid & 1;         // 0..1 : 64-hid tile
    const int grp = lane >> 2;       // 0..7
    const int kp  = lane & 3;        // 0..3

    const int lrow = lane & 15;
    const int lcol = (lane >> 4) * 4;     // u32: +4 => k+8
    const uint32_t aOff = (uint32_t)(((wm * 16 + lrow) * KSTR + lcol) * 4);
    uint32_t bOff[4];
#pragma unroll
    for (int pi = 0; pi < 4; pi++)
        bOff[pi] = (uint32_t)(((wn * 64 + pi * 16 + lrow) * KSTR + lcol) * 4);

    auto issue = [&](int c, int buf) {
        uint32_t base = sb + G_OFF_T + buf * G_BUF;
        {
            int b = tid >> 2, q = tid & 3;   // 64 x 4 = 256
            size_t go = (size_t)(m0 + b) * INP + c * 32 + q * 8;
            uint32_t so = (uint32_t)((b * KSTR + q * 4) * 4);
            cp16(base + so,          g_xH + go);
            cp16(base + G_XSZ + so,  g_xL + go);
        }
#pragma unroll
        for (int rep = 0; rep < 2; rep++) {  // 128 x 4 = 512
            int i = tid + rep * 256;
            int n = i >> 2, q = i & 3;
            size_t go = (size_t)n * INP + c * 32 + q * 8;
            uint32_t so = (uint32_t)((n * KSTR + q * 4) * 4);
            cp16(base + 2 * G_XSZ + so,          g_w1H + go);
            cp16(base + 2 * G_XSZ + G_WSZ + so,  g_w1L + go);
        }
    };

    float acc[8][4];
#pragma unroll
    for (int ni = 0; ni < 8; ni++)
#pragma unroll
        for (int r = 0; r < 4; r++) acc[ni][r] = 0.f;

    issue(0, 0);
    cp_commit();

    for (int c = 0; c < G_NC; c++) {
        cp_wait0();
        __syncthreads();
        if (c + 1 < G_NC) { issue(c + 1, (c + 1) & 1); cp_commit(); }

        uint32_t xhB = sb + G_OFF_T + (c & 1) * G_BUF;
        uint32_t xlB = xhB + G_XSZ;
        uint32_t whB = xlB + G_XSZ;
        uint32_t wlB = whB + G_WSZ;

#pragma unroll
        for (int s = 0; s < 2; s++) {
            uint32_t sB = s * 32;
            uint32_t ah0, ah1, ah2, ah3, al0, al1, al2, al3;
            ldsm4(ah0, ah1, ah2, ah3, xhB + aOff + sB);
            ldsm4(al0, al1, al2, al3, xlB + aOff + sB);
#pragma unroll
            for (int pi = 0; pi < 4; pi++) {
                uint32_t h0, h1, h2, h3, l0, l1, l2, l3;
                ldsm4(h0, h1, h2, h3, whB + bOff[pi] + sB);
                ldsm4(l0, l1, l2, l3, wlB + bOff[pi] + sB);
                mma16816(acc[2 * pi],     ah0, ah1, ah2, ah3, h0, h2);
                mma16816(acc[2 * pi],     al0, al1, al2, al3, h0, h2);
                mma16816(acc[2 * pi],     ah0, ah1, ah2, ah3, l0, l2);
                mma16816(acc[2 * pi + 1], ah0, ah1, ah2, ah3, h1, h3);
                mma16816(acc[2 * pi + 1], al0, al1, al2, al3, h1, h3);
                mma16816(acc[2 * pi + 1], ah0, ah1, ah2, ah3, l1, l3);
            }
        }
    }

    // epilogue: bias + relu -> feats fp32 + bf16 hi/lo
    const int rowA = m0 + wm * 16 + grp;
#pragma unroll
    for (int ni = 0; ni < 8; ni++) {
        int col = wn * 64 + ni * 8 + kp * 2;
        float c0 = sBias[col], c1 = sBias[col + 1];
#pragma unroll
        for (int half = 0; half < 2; half++) {
            int row = rowA + half * 8;
            float v0 = acc[ni][2 * half]     + c0;
            float v1 = acc[ni][2 * half + 1] + c1;
            v0 = v0 > 0.f ? v0 : 0.f;
            v1 = v1 > 0.f ? v1 : 0.f;
            *(float2*)&g_feats[(size_t)row * HID + col] = make_float2(v0, v1);
            unsigned h0 = bf16_bits(v0), h1 = bf16_bits(v1);
            unsigned l0 = bf16_bits(v0 - bf16_val(h0));
            unsigned l1 = bf16_bits(v1 - bf16_val(h1));
            *(uint32_t*)&g_fH[(size_t)row * HID + col] = h0 | (h1 << 16);
            *(uint32_t*)&g_fL[(size_t)row * HID + col] = l0 | (l1 << 16);
        }
    }
}

// ---------------------------------------------------------------------------
// Prediction: pred = feats @ W2 + b2   (32 rows/block, grid 256)
// ---------------------------------------------------------------------------
__global__ __launch_bounds__(256) void pred_kernel(const float* __restrict__ W2,
                                                   const float* __restrict__ b2,
                                                   float* __restrict__ pred) {
    __shared__ float sF[32 * 132];
    __shared__ float sW2[HID * CLASS_NUM];
    const int tid = threadIdx.x;
    const int b0  = blockIdx.x * 32;
#pragma unroll
    for (int it = 0; it < 16; it++) {
        int e = it * 256 + tid;
        int r = e >> 7, d = e & 127;
        sF[r * 132 + d] = g_feats[(size_t)(b0 + r) * HID + d];
    }
    for (int e = tid; e < HID * CLASS_NUM; e += 256) sW2[e] = W2[e];
    __syncthreads();
    for (int o = tid; o < 32 * CLASS_NUM; o += 256) {
        int r = o / CLASS_NUM, c = o % CLASS_NUM;
        float s = b2[c];
#pragma unroll 8
        for (int d = 0; d < HID; d++) s += sF[r * 132 + d] * sW2[d * CLASS_NUM + c];
        pred[(size_t)(b0 + r) * CLASS_NUM + c] = s;
    }
}

// ---------------------------------------------------------------------------
// Tree kernel (mma.sync bf16, 3-term split, ldmatrix, cp.async dbuf):
//   per (tree, 64-batch tile): D[64b x 256n] -> sigmoid -> dec tile -> DFS
//   dec tile ALIASES the MMA tile buffers -> 2 CTAs/SM
//   DFS: float2 path products (2 cols/thread), streaming stores
// ---------------------------------------------------------------------------
#define MB    64
#define DSTR  68
#define T_NC  (HID / 32)               // 4

#define T_OFF_NB  0
#define T_OFF_T   1024
#define T_FSZ     (64 * KSTR * 4)            // 5120
#define T_WSZ     (256 * KSTR * 4)           // 20480
#define T_BUF     (2 * T_FSZ + 2 * T_WSZ)    // 51200
#define TREE_SMEM (T_OFF_T + 2 * T_BUF)      // 103424

template <int LVL>
__device__ __forceinline__ void emit2(float* __restrict__ outCol,
                                      const float* __restrict__ decCol,
                                      int node, float2 v) {
    stcs2(&outCol[(size_t)node * BATCH], v);
    if constexpr (LVL < DEPTH - 1) {
        float2 d = *(const float2*)&decCol[node * DSTR];
        emit2<LVL + 1>(outCol, decCol, 2 * node + 1,
                       make_float2(v.x * d.x, v.y * d.y));
        emit2<LVL + 1>(outCol, decCol, 2 * node + 2,
                       make_float2(v.x * (1.f - d.x), v.y * (1.f - d.y)));
    }
}

__global__ __launch_bounds__(512, 2) void tree_mma_kernel(const float* __restrict__ nodeb,
                                                          float* __restrict__ outAll) {
    extern __shared__ char smem[];
    float* sNB  = (float*)(smem + T_OFF_NB);
    float* decS = (float*)(smem + T_OFF_T);   // aliases tile buffers (post-MMA)
    const uint32_t sb = smem_u32(smem);

    const int tid  = threadIdx.x;
    const int wid  = tid >> 5;
    const int lane = tid & 31;
    const int t    = blockIdx.y;
    const int b0   = blockIdx.x * MB;
    const size_t wbase = (size_t)t * 256 * HID;

    if (tid < 256)
        sNB[tid] = (tid < INTERNAL) ? nodeb[t * INTERNAL + tid] : 0.f;

    const int wb  = wid >> 2;      // 0..3: 16-batch tile
    const int wn  = wid & 3;       // 0..3: 64-node tile
    const int grp = lane >> 2;
    const int kp  = lane & 3;

    const int lrow = lane & 15;
    const int lcol = (lane >> 4) * 4;
    const uint32_t aOff = (uint32_t)(((wb * 16 + lrow) * KSTR + lcol) * 4);
    uint32_t bOff[4];
#pragma unroll
    for (int pi = 0; pi < 4; pi++)
        bOff[pi] = (uint32_t)(((wn * 64 + pi * 16 + lrow) * KSTR + lcol) * 4);

    auto issue = [&](int c, int buf) {
        uint32_t base = sb + T_OFF_T + buf * T_BUF;
        {
            int i = tid & 255, b = i >> 2, q = i & 3;
            size_t go = (size_t)(b0 + b) * HID + c * 32 + q * 8;
            uint32_t so = (uint32_t)((b * KSTR + q * 4) * 4);
            if (tid < 256) cp16(base + so,         g_fH + go);
            else           cp16(base + T_FSZ + so, g_fL + go);
        }
#pragma unroll
        for (int rep = 0; rep < 2; rep++) {
            int i = tid + rep * 512;
            int n = i >> 2, q = i & 3;
            size_t go = wbase + (size_t)n * HID + c * 32 + q * 8;
            uint32_t so = (uint32_t)((n * KSTR + q * 4) * 4);
            cp16(base + 2 * T_FSZ + so,          g_nwH + go);
            cp16(base + 2 * T_FSZ + T_WSZ + so,  g_nwL + go);
        }
    };

    float acc[8][4];
#pragma unroll
    for (int ni = 0; ni < 8; ni++)
#pragma unroll
        for (int r = 0; r < 4; r++) acc[ni][r] = 0.f;

    issue(0, 0);
    cp_commit();

#pragma unroll
    for (int c = 0; c < T_NC; c++) {
        cp_wait0();
        __syncthreads();
        if (c + 1 < T_NC) { issue(c + 1, (c + 1) & 1); cp_commit(); }

        uint32_t fhB = sb + T_OFF_T + (c & 1) * T_BUF;
        uint32_t flB = fhB + T_FSZ;
        uint32_t whB = flB + T_FSZ;
        uint32_t wlB = whB + T_WSZ;

#pragma unroll
        for (int s = 0; s < 2; s++) {
            uint32_t sB = s * 32;
            uint32_t ah0, ah1, ah2, ah3, al0, al1, al2, al3;
            ldsm4(ah0, ah1, ah2, ah3, fhB + aOff + sB);
            ldsm4(al0, al1, al2, al3, flB + aOff + sB);
#pragma unroll
            for (int pi = 0; pi < 4; pi++) {
                uint32_t h0, h1, h2, h3, l0, l1, l2, l3;
                ldsm4(h0, h1, h2, h3, whB + bOff[pi] + sB);
                ldsm4(l0, l1, l2, l3, wlB + bOff[pi] + sB);
                mma16816(acc[2 * pi],     ah0, ah1, ah2, ah3, h0, h2);
                mma16816(acc[2 * pi],     al0, al1, al2, al3, h0, h2);
                mma16816(acc[2 * pi],     ah0, ah1, ah2, ah3, l0, l2);
                mma16816(acc[2 * pi + 1], ah0, ah1, ah2, ah3, h1, h3);
                mma16816(acc[2 * pi + 1], al0, al1, al2, al3, h1, h3);
                mma16816(acc[2 * pi + 1], ah0, ah1, ah2, ah3, l1, l3);
            }
        }
    }

    // dec tile aliases the MMA buffers: all compute must be done first
    __syncthreads();

    // ---- epilogue: + bias, sigmoid -> dec tile ----
#pragma unroll
    for (int ni = 0; ni < 8; ni++) {
        int nbase = wn * 64 + ni * 8 + kp * 2;
        int bb    = wb * 16 + grp;
#pragma unroll
        for (int r = 0; r < 4; r++) {
            int node = nbase + (r & 1);
            int b    = bb + (r >> 1) * 8;
            if (node < INTERNAL)
                decS[node * DSTR + b] = sigmoidf_(acc[ni][r] + sNB[node]);
        }
    }
    __syncthreads();

    // ---- tree path products: 32 col-pairs x 16 groups, float2 ----
    {
        const int colp = (tid & 31) * 2;       // 0,2,..,62
        const int q    = tid >> 5;             // 0..15
        float* outCol = outAll + (size_t)t * TOTAL * BATCH + (b0 + colp);
        const float* decCol = decS + colp;

        if (q < 8) {
            // subtree rooted at level-3 node 7+q: 63 nodes
            const int rN = 7 + q;
            float2 v = make_float2(1.f, 1.f);
            int x = rN;
            while (x) {
                int p = (x - 1) >> 1;
                float2 d = *(const float2*)&decCol[p * DSTR];
                if (x == 2 * p + 1) { v.x *= d.x;        v.y *= d.y; }
                else                { v.x *= 1.f - d.x;  v.y *= 1.f - d.y; }
                x = p;
            }
            emit2<3>(outCol, decCol, rN, v);
        } else {
            // top 7 nodes (levels 0..2): group q-8 handles node q-8
            const int n = q - 8;
            if (n < 7) {
                float2 v = make_float2(1.f, 1.f);
                int x = n;
                while (x) {
                    int p = (x - 1) >> 1;
                    float2 d = *(const float2*)&decCol[p * DSTR];
                    if (x == 2 * p + 1) { v.x *= d.x;        v.y *= d.y; }
                    else                { v.x *= 1.f - d.x;  v.y *= 1.f - d.y; }
                    x = p;
                }
                stcs2(&outCol[(size_t)n * BATCH], v);
            }
        }
    }
}

// ---------------------------------------------------------------------------
extern "C" void kernel_launch(void* const* d_in, const int* in_sizes, int n_in,
                              void* d_out, int out_size) {
    const float* X     = (const float*)d_in[0];
    const float* W1    = (const float*)d_in[1];
    const float* b1    = (const float*)d_in[2];
    const float* W2    = (const float*)d_in[3];
    const float* b2    = (const float*)d_in[4];
    const float* nodeW = (const float*)d_in[5];
    const float* nodeb = (const float*)d_in[6];

    float* pred   = (float*)d_out;                               // [8192, 10]
    float* outAll = (float*)d_out + (size_t)BATCH * CLASS_NUM;   // [16, 511, 8192]

    cudaFuncSetAttribute(tree_mma_kernel, cudaFuncAttributeMaxDynamicSharedMemorySize,
                         TREE_SMEM);
    cudaFuncSetAttribute(gemm1_mma_kernel, cudaFuncAttributeMaxDynamicSharedMemorySize,
                         G_SMEM);

    conv_X_kernel<<<BATCH, 256>>>(X);
    conv_W1_kernel<<<HID, 256>>>(W1);
    conv_nodeW_kernel<<<TREES * 256 * HID / 256, 256>>>(nodeW);
    gemm1_mma_kernel<<<BATCH / G_MB, 256, G_SMEM>>>(b1);
    tree_mma_kernel<<<dim3(BATCH / MB, TREES), 512, TREE_SMEM>>>(nodeb, outAll);
    pred_kernel<<<BATCH / 32, 256>>>(W2, b2, pred);
}